// round 14
// baseline (speedup 1.0000x reference)
#include <cuda_runtime.h>
#include <math.h>
#include <math_constants.h>

#define D_MODEL 768
#define N_BR    4
#define DH      64
#define H_TOT   48
#define BATCH   2
#define T_LEN   1024
#define M_ROWS  2048
#define NQ      3072

typedef unsigned long long u64;
typedef unsigned int u32;

// ---- packed fp32x2 helpers ----
__device__ __forceinline__ u64 f2fma(u64 a, u64 b, u64 c) {
    u64 d; asm("fma.rn.f32x2 %0, %1, %2, %3;" : "=l"(d) : "l"(a), "l"(b), "l"(c)); return d;
}
__device__ __forceinline__ u64 f2add(u64 a, u64 b) {
    u64 d; asm("add.rn.f32x2 %0, %1, %2;" : "=l"(d) : "l"(a), "l"(b)); return d;
}
__device__ __forceinline__ u64 f2pack(float lo, float hi) {
    u64 d; asm("mov.b64 %0, {%1, %2};" : "=l"(d) : "f"(lo), "f"(hi)); return d;
}
__device__ __forceinline__ float2 f2unpack(u64 a) {
    float lo, hi; asm("mov.b64 {%0, %1}, %2;" : "=f"(lo), "=f"(hi) : "l"(a)); return make_float2(lo, hi);
}
__device__ __forceinline__ float f2sum(u64 a) { float2 v = f2unpack(a); return v.x + v.y; }

// ---- tf32 split ----
__device__ __forceinline__ float2 tf32split(float x) {
    u32 hb; asm("cvt.rna.tf32.f32 %0, %1;" : "=r"(hb) : "f"(x));
    float hf = __uint_as_float(hb);
    float lo = x - hf;
    u32 lb; asm("cvt.rna.tf32.f32 %0, %1;" : "=r"(lb) : "f"(lo));
    return make_float2(hf, __uint_as_float(lb));
}

#define MMA_TF32(ACC, A0, A1, A2, A3, B0, B1)                                        \
    asm volatile("mma.sync.aligned.m16n8k8.row.col.f32.tf32.tf32.f32 "               \
                 "{%0,%1,%2,%3}, {%4,%5,%6,%7}, {%8,%9}, {%0,%1,%2,%3};"             \
                 : "+f"(ACC[0]), "+f"(ACC[1]), "+f"(ACC[2]), "+f"(ACC[3])            \
                 : "r"(A0), "r"(A1), "r"(A2), "r"(A3), "r"(B0), "r"(B1))

// ---- scratch ----
__device__ float  g_wq2f[NQ * D_MODEL];
__device__ float  g_wk2f[NQ * D_MODEL];
__device__ float  g_bk2 [NQ];
__device__ float  g_wotf[D_MODEL * NQ];
__device__ float  g_v2t [256 * DH];            // V2 transposed: [j][d]
__device__ float  g_qf  [(size_t)M_ROWS * NQ];
__device__ float  g_kf  [(size_t)M_ROWS * NQ];
__device__ float  g_ctx [(size_t)M_ROWS * NQ];
__device__ float  g_part[(size_t)N_BR * M_ROWS * D_MODEL];
__device__ float2 g_ropetab[T_LEN * 32];
__device__ int4   g_topi [BATCH * H_TOT * T_LEN];
__device__ float4 g_topw [BATCH * H_TOT * T_LEN];
__device__ float  g_psink[BATCH * H_TOT * T_LEN];

// ================= prep_w: wedge folds + WO relayout + rope table + V2 transpose =
__global__ __launch_bounds__(256) void prep_w(const float* __restrict__ WQw,
                                              const float* __restrict__ WKw,
                                              const float* __restrict__ WKb,
                                              const float* __restrict__ wedgeA,
                                              const float* __restrict__ wbias,
                                              const float* __restrict__ WOw,
                                              const float* __restrict__ V2w) {
    __shared__ float sk[4096];
    __shared__ float Ws[64 * 68];
    __shared__ float tile[32][33];
    const int blk = blockIdx.x, tid = threadIdx.x;

    if (blk < 1152) {
        const bool isK = blk >= 576;
        const int b2 = isK ? blk - 576 : blk;
        const int h = b2 / 12, c0 = (b2 % 12) * 64;
        const int hs = isK ? (h % 12) : h;
        const float* Wsrc = isK ? WKw : WQw;
        for (int i = tid; i < 4096; i += 256) {
            int e = i >> 6, d = i & 63;
            sk[i] = wedgeA[e * 64 + d] - wedgeA[d * 64 + e];
        }
        for (int i = tid; i < 4096; i += 256) {
            int e = i >> 6, c = i & 63;
            Ws[e * 68 + c] = Wsrc[(size_t)(hs * 64 + e) * D_MODEL + c0 + c];
        }
        __syncthreads();
        const int d = tid >> 2, cg = (tid & 3) * 16;
        float outv[16];
        const float bd = 1.0f + wbias[h * 64 + d];
#pragma unroll
        for (int u = 0; u < 16; u++) outv[u] = bd * Ws[d * 68 + cg + u];
        for (int e = 0; e < 64; ++e) {
            float s = sk[e * 64 + d];
            const float* wr = &Ws[e * 68 + cg];
#pragma unroll
            for (int u = 0; u < 16; u++) outv[u] = fmaf(s, wr[u], outv[u]);
        }
        float* dst = (isK ? g_wk2f : g_wq2f) + (size_t)(h * 64 + d) * D_MODEL + c0 + cg;
#pragma unroll
        for (int u = 0; u < 16; u++) dst[u] = outv[u];

        if (isK && c0 == 0 && tid < 64) {
            float acc = (1.0f + wbias[h * 64 + tid]) * WKb[hs * 64 + tid];
            for (int s = 0; s < 64; ++s) acc += sk[s * 64 + tid] * WKb[hs * 64 + s];
            g_bk2[h * 64 + tid] = acc;
        }
    } else if (blk < 3456) {
        const int b3 = blk - 1152;
        const int br = b3 / 576, rem = b3 % 576;
        const int cb = (rem / 24) * 32, nb = (rem % 24) * 32;
        const int tx = tid & 31, ty = tid >> 5;
        for (int r = ty; r < 32; r += 8)
            tile[r][tx] = WOw[((size_t)br * D_MODEL + cb + r) * D_MODEL + nb + tx];
        __syncthreads();
        for (int r = ty; r < 32; r += 8)
            g_wotf[(size_t)(nb + r) * NQ + br * D_MODEL + cb + tx] = tile[tx][r];
    } else if (blk < 3472) {
        // V2 transpose: [64][256] -> [256][64]
        int idx = (blk - 3456) * 1024 + tid * 4;
#pragma unroll
        for (int u = 0; u < 4; u++) {
            int j = (idx + u) >> 6, d = (idx + u) & 63;
            g_v2t[(idx + u)] = 0.0f;  // placeholder; overwritten below
            g_v2t[j * 64 + d] = V2w[d * 256 + j];
        }
    } else {
        // rope table: blocks 3472..3599
        int idx = (blk - 3472) * 256 + tid;
        int t = idx >> 5, i = idx & 31;
        float inv = exp2f(-(float)i * 0.41524101186092034f);
        float fr = (float)t * inv;
        g_ropetab[idx] = make_float2(cosf(fr), sinf(fr));
    }
}

// ================= tf32-3x NT GEMM, double-buffered, in-loop split ===============
template <int MODE>
__global__ __launch_bounds__(256) void gemm_tf32_kernel(const float* __restrict__ A0,
                                                        const float* __restrict__ A1,
                                                        int K) {
    extern __shared__ float2 smg[];
    float2* Abuf = smg;            // 2 x 16*132
    float2* Bbuf = smg + 4224;     // 2 x 16*68

    const int tid = threadIdx.x;
    const int m0 = blockIdx.y * 128, n0 = blockIdx.x * 64;
    const int warpId = tid >> 5, lane = tid & 31;
    const int warpM = warpId & 3, warpN = warpId >> 2;
    const int g = lane >> 2, tg = lane & 3;
    const int sa_m = tid >> 1, sa_k = (tid & 1) * 8;
    const int sb_n = tid & 63, sb_k = (tid >> 6) * 4;

    const float* Aop;
    const float* Bop;
    int ldA, ldB;
    if (MODE == 0) {
        Aop = blockIdx.z ? A1 : A0;
        Bop = blockIdx.z ? g_wk2f : g_wq2f;
        ldA = 768; ldB = 768;
    } else {
        Aop = g_ctx  + blockIdx.z * 768;
        Bop = g_wotf + blockIdx.z * 768;
        ldA = 3072; ldB = 3072;
    }

    float acc[2][4][4];
#pragma unroll
    for (int mf = 0; mf < 2; mf++)
#pragma unroll
        for (int nf = 0; nf < 4; nf++)
#pragma unroll
            for (int r = 0; r < 4; r++) acc[mf][nf][r] = 0.f;

    const float* Arow = Aop + (size_t)(m0 + sa_m) * ldA + sa_k;
    const float* Brow = Bop + (size_t)(n0 + sb_n) * ldB + sb_k;

    float4 pa0 = *(const float4*)(Arow);
    float4 pa1 = *(const float4*)(Arow + 4);
    float4 pb  = *(const float4*)(Brow);

    {
        float av[8] = {pa0.x, pa0.y, pa0.z, pa0.w, pa1.x, pa1.y, pa1.z, pa1.w};
#pragma unroll
        for (int j = 0; j < 8; j++) Abuf[(sa_k + j) * 132 + sa_m] = tf32split(av[j]);
        float bv[4] = {pb.x, pb.y, pb.z, pb.w};
#pragma unroll
        for (int j = 0; j < 4; j++) Bbuf[(sb_k + j) * 68 + sb_n] = tf32split(bv[j]);
    }
    __syncthreads();

    int p = 0;
    for (int k0 = 0; k0 < K; k0 += 16) {
        const bool more = (k0 + 16) < K;
        if (more) {
            pa0 = *(const float4*)(Arow + k0 + 16);
            pa1 = *(const float4*)(Arow + k0 + 20);
            pb  = *(const float4*)(Brow + k0 + 16);
        }
        const float2* As2 = Abuf + p * 2112;
        const float2* Bs2 = Bbuf + p * 1088;
#pragma unroll
        for (int ks = 0; ks < 16; ks += 8) {
            float2 fa[2][4];
#pragma unroll
            for (int mf = 0; mf < 2; mf++) {
                const int rI = warpM * 32 + mf * 16 + g;
                const float2* c0p = &As2[(ks + tg) * 132];
                const float2* c4p = &As2[(ks + tg + 4) * 132];
                fa[mf][0] = c0p[rI];
                fa[mf][1] = c0p[rI + 8];
                fa[mf][2] = c4p[rI];
                fa[mf][3] = c4p[rI + 8];
            }
            float2 fb[4][2];
#pragma unroll
            for (int nf = 0; nf < 4; nf++) {
                const int cI = warpN * 32 + nf * 8 + g;
                fb[nf][0] = Bs2[(ks + tg) * 68 + cI];
                fb[nf][1] = Bs2[(ks + tg + 4) * 68 + cI];
            }
#pragma unroll
            for (int mf = 0; mf < 2; mf++) {
                const u32 ah0 = __float_as_uint(fa[mf][0].x), al0 = __float_as_uint(fa[mf][0].y);
                const u32 ah1 = __float_as_uint(fa[mf][1].x), al1 = __float_as_uint(fa[mf][1].y);
                const u32 ah2 = __float_as_uint(fa[mf][2].x), al2 = __float_as_uint(fa[mf][2].y);
                const u32 ah3 = __float_as_uint(fa[mf][3].x), al3 = __float_as_uint(fa[mf][3].y);
#pragma unroll
                for (int nf = 0; nf < 4; nf++) {
                    const u32 bh0 = __float_as_uint(fb[nf][0].x), bl0 = __float_as_uint(fb[nf][0].y);
                    const u32 bh1 = __float_as_uint(fb[nf][1].x), bl1 = __float_as_uint(fb[nf][1].y);
                    MMA_TF32(acc[mf][nf], al0, al1, al2, al3, bh0, bh1);
                    MMA_TF32(acc[mf][nf], ah0, ah1, ah2, ah3, bl0, bl1);
                    MMA_TF32(acc[mf][nf], ah0, ah1, ah2, ah3, bh0, bh1);
                }
            }
        }
        if (more) {
            float2* An = Abuf + (p ^ 1) * 2112;
            float2* Bn = Bbuf + (p ^ 1) * 1088;
            float av[8] = {pa0.x, pa0.y, pa0.z, pa0.w, pa1.x, pa1.y, pa1.z, pa1.w};
#pragma unroll
            for (int j = 0; j < 8; j++) An[(sa_k + j) * 132 + sa_m] = tf32split(av[j]);
            float bv[4] = {pb.x, pb.y, pb.z, pb.w};
#pragma unroll
            for (int j = 0; j < 4; j++) Bn[(sb_k + j) * 68 + sb_n] = tf32split(bv[j]);
            __syncthreads();
        }
        p ^= 1;
    }

    // ---- epilogue ----
#pragma unroll
    for (int mf = 0; mf < 2; mf++) {
#pragma unroll
        for (int nf = 0; nf < 4; nf++) {
            const int r0 = m0 + warpM * 32 + mf * 16 + g;
            const int r1 = r0 + 8;
            float c0 = acc[mf][nf][0], c1 = acc[mf][nf][1];
            float c2 = acc[mf][nf][2], c3 = acc[mf][nf][3];
            if (MODE == 0) {
                const int h = blockIdx.x;
                const int i = warpN * 16 + nf * 4 + tg;
                float* dstbase = blockIdx.z ? g_kf : g_qf;
                if (blockIdx.z) {
                    const float b0 = g_bk2[h * 64 + 2 * i];
                    const float b1 = g_bk2[h * 64 + 2 * i + 1];
                    c0 += b0; c1 += b1; c2 += b0; c3 += b1;
                }
                {
                    const int t = r0 & 1023, bb = r0 >> 10;
                    float2 rc = g_ropetab[t * 32 + i];
                    float* qp = &dstbase[(((size_t)(bb * H_TOT + h)) * T_LEN + t) * DH];
                    qp[i]      = c0 * rc.x - c1 * rc.y;
                    qp[i + 32] = c0 * rc.y + c1 * rc.x;
                }
                {
                    const int t = r1 & 1023, bb = r1 >> 10;
                    float2 rc = g_ropetab[t * 32 + i];
                    float* qp = &dstbase[(((size_t)(bb * H_TOT + h)) * T_LEN + t) * DH];
                    qp[i]      = c2 * rc.x - c3 * rc.y;
                    qp[i + 32] = c2 * rc.y + c3 * rc.x;
                }
            } else {
                const int nc = n0 + warpN * 32 + nf * 8 + 2 * tg;
                float* base = g_part + (size_t)blockIdx.z * M_ROWS * D_MODEL;
                *(float2*)&base[(size_t)r0 * 768 + nc] = make_float2(c0, c1);
                *(float2*)&base[(size_t)r1 * 768 + nc] = make_float2(c2, c3);
            }
        }
    }
}

// ================= reduce =================
__global__ __launch_bounds__(256) void reduce_kernel(const float* __restrict__ WOb,
                                                     float* __restrict__ Y) {
    const size_t i4 = (size_t)blockIdx.x * 256 + threadIdx.x;
    const size_t base = i4 * 4;
    const int nc = (int)(base % 768);
    float4 p0 = *(const float4*)&g_part[base];
    float4 p1 = *(const float4*)&g_part[base + (size_t)M_ROWS * D_MODEL];
    float4 p2 = *(const float4*)&g_part[base + (size_t)2 * M_ROWS * D_MODEL];
    float4 p3 = *(const float4*)&g_part[base + (size_t)3 * M_ROWS * D_MODEL];
    float4 o;
    o.x = 0.25f * (p0.x + p1.x + p2.x + p3.x) + 0.25f * (WOb[nc]     + WOb[768 + nc]     + WOb[1536 + nc]     + WOb[2304 + nc]);
    o.y = 0.25f * (p0.y + p1.y + p2.y + p3.y) + 0.25f * (WOb[nc + 1] + WOb[768 + nc + 1] + WOb[1536 + nc + 1] + WOb[2304 + nc + 1]);
    o.z = 0.25f * (p0.z + p1.z + p2.z + p3.z) + 0.25f * (WOb[nc + 2] + WOb[768 + nc + 2] + WOb[1536 + nc + 2] + WOb[2304 + nc + 2]);
    o.w = 0.25f * (p0.w + p1.w + p2.w + p3.w) + 0.25f * (WOb[nc + 3] + WOb[768 + nc + 3] + WOb[1536 + nc + 3] + WOb[2304 + nc + 3]);
    *(float4*)&Y[base] = o;
}

// ---- online softmax + top-4 update ----
#define SMTK_UPDATE(sc, sidx, mrun, lrun, s0v, s1v, s2v, s3v, i0v, i1v, i2v, i3v) \
    do {                                                                          \
        if ((sc) <= (mrun)) { (lrun) += __expf((sc) - (mrun)); }                  \
        else { (lrun) = fmaf((lrun), __expf((mrun) - (sc)), 1.0f); (mrun) = (sc); } \
        if ((sc) > (s3v)) {                                                       \
            if ((sc) > (s2v)) {                                                   \
                (s3v) = (s2v); (i3v) = (i2v);                                     \
                if ((sc) > (s1v)) {                                               \
                    (s2v) = (s1v); (i2v) = (i1v);                                 \
                    if ((sc) > (s0v)) {                                           \
                        (s1v) = (s0v); (i1v) = (i0v);                             \
                        (s0v) = (sc); (i0v) = (sidx);                             \
                    } else { (s1v) = (sc); (i1v) = (sidx); }                      \
                } else { (s2v) = (sc); (i2v) = (sidx); }                          \
            } else { (s3v) = (sc); (i3v) = (sidx); }                              \
        }                                                                         \
    } while (0)

#define MERGE_INS(sc, ix)                                                         \
    do {                                                                          \
        if ((sc) > bs3 || ((sc) == bs3 && (ix) < bi3)) {                          \
            if ((sc) > bs2 || ((sc) == bs2 && (ix) < bi2)) {                      \
                bs3 = bs2; bi3 = bi2;                                             \
                if ((sc) > bs1 || ((sc) == bs1 && (ix) < bi1)) {                  \
                    bs2 = bs1; bi2 = bi1;                                         \
                    if ((sc) > bs0 || ((sc) == bs0 && (ix) < bi0)) {              \
                        bs1 = bs0; bi1 = bi0; bs0 = (sc); bi0 = (ix);             \
                    } else { bs1 = (sc); bi1 = (ix); }                            \
                } else { bs2 = (sc); bi2 = (ix); }                                \
            } else { bs3 = (sc); bi3 = (ix); }                                    \
        }                                                                         \
    } while (0)

// ================= attn1: R11 form (4-way s-phase split, LDS.128 k reads) ========
__global__ __launch_bounds__(512) void attn1_kernel(const float* __restrict__ sink) {
    extern __shared__ float ks[];            // 8192 floats
    const int bh = blockIdx.y, h = bh % H_TOT;
    const int xt = (gridDim.x - 1) - blockIdx.x;
    const int t0 = xt * 128;
    const int tid = threadIdx.x;
    const int row = tid & 127;
    const int ph  = tid >> 7;                // 0..3
    const int tA = t0 + row;

    u64 q2[32];
    {
        const ulonglong2* qp = (const ulonglong2*)&g_qf[((size_t)bh * T_LEN + tA) * DH];
#pragma unroll
        for (int i = 0; i < 16; i++) { ulonglong2 v = qp[i]; q2[2 * i] = v.x; q2[2 * i + 1] = v.y; }
    }

    float mrun = -CUDART_INF_F, lrun = 0.f;
    float ts0 = -CUDART_INF_F, ts1 = -CUDART_INF_F, ts2 = -CUDART_INF_F, ts3 = -CUDART_INF_F;
    int ti0 = 0, ti1 = 0, ti2 = 0, ti3 = 0;

    for (int s0 = 0; s0 <= t0; s0 += 128) {
        __syncthreads();
        {
            const float4* kg = (const float4*)&g_kf[((size_t)bh * T_LEN + s0) * DH];
            float4* d4 = (float4*)ks;
#pragma unroll
            for (int j = 0; j < 4; j++) d4[tid + j * 512] = kg[tid + j * 512];
        }
        __syncthreads();

        const int sMax = min(tA, s0 + 127);
        for (int s = s0 + ph; s <= sMax; s += 4) {
            const ulonglong2* kr = (const ulonglong2*)(ks + (s - s0) * DH);
            u64 a0 = 0ull, a1 = 0ull, a2 = 0ull, a3 = 0ull;
#pragma unroll
            for (int i = 0; i < 16; i += 4) {
                ulonglong2 k01 = kr[i];
                ulonglong2 k23 = kr[i + 1];
                ulonglong2 k45 = kr[i + 2];
                ulonglong2 k67 = kr[i + 3];
                a0 = f2fma(q2[2 * i],     k01.x, a0);
                a1 = f2fma(q2[2 * i + 1], k01.y, a1);
                a2 = f2fma(q2[2 * i + 2], k23.x, a2);
                a3 = f2fma(q2[2 * i + 3], k23.y, a3);
                a0 = f2fma(q2[2 * i + 4], k45.x, a0);
                a1 = f2fma(q2[2 * i + 5], k45.y, a1);
                a2 = f2fma(q2[2 * i + 6], k67.x, a2);
                a3 = f2fma(q2[2 * i + 7], k67.y, a3);
            }
            u64 s01 = f2add(a0, a1);
            u64 s23 = f2add(a2, a3);
            float2 sv = f2unpack(f2add(s01, s23));
            float sc = (sv.x + sv.y) * 0.125f;
            SMTK_UPDATE(sc, s, mrun, lrun, ts0, ts1, ts2, ts3, ti0, ti1, ti2, ti3);
        }
    }

    // ---- merge 4 phases per row ----
    __syncthreads();
    float* Pm = ks;
    float* Pl = ks + 512;
    float* Ps = ks + 1024;
    int*   Pi = (int*)(ks + 3072);
    Pm[tid] = mrun; Pl[tid] = lrun;
    Ps[tid * 4 + 0] = ts0; Ps[tid * 4 + 1] = ts1; Ps[tid * 4 + 2] = ts2; Ps[tid * 4 + 3] = ts3;
    Pi[tid * 4 + 0] = ti0; Pi[tid * 4 + 1] = ti1; Pi[tid * 4 + 2] = ti2; Pi[tid * 4 + 3] = ti3;
    __syncthreads();

    if (tid < 128) {
        float m0v = Pm[tid], m1v = Pm[tid + 128], m2v = Pm[tid + 256], m3v = Pm[tid + 384];
        float mm = fmaxf(fmaxf(m0v, m1v), fmaxf(m2v, m3v));
        float ll = Pl[tid]       * __expf(m0v - mm)
                 + Pl[tid + 128] * __expf(m1v - mm)
                 + Pl[tid + 256] * __expf(m2v - mm)
                 + Pl[tid + 384] * __expf(m3v - mm);

        float bs0 = -CUDART_INF_F, bs1 = -CUDART_INF_F, bs2 = -CUDART_INF_F, bs3 = -CUDART_INF_F;
        int bi0 = 0x7fffffff, bi1 = 0x7fffffff, bi2 = 0x7fffffff, bi3 = 0x7fffffff;
#pragma unroll
        for (int pp = 0; pp < 4; pp++) {
            const int pidx = pp * 128 + tid;
#pragma unroll
            for (int j = 0; j < 4; j++) {
                float sc = Ps[pidx * 4 + j];
                int   ix = Pi[pidx * 4 + j];
                MERGE_INS(sc, ix);
            }
        }
        if (bi0 == 0x7fffffff) bi0 = 0;
        if (bi1 == 0x7fffffff) bi1 = 0;
        if (bi2 == 0x7fffffff) bi2 = 0;
        if (bi3 == 0x7fffffff) bi3 = 0;

        const float skv = sink[h];
        const float mf = fmaxf(mm, skv);
        const float Z = ll * __expf(mm - mf) + __expf(skv - mf);
        const float invZ = 1.0f / Z;
        float p0 = __expf(bs0 - mf) * invZ;
        float p1 = __expf(bs1 - mf) * invZ;
        float p2 = __expf(bs2 - mf) * invZ;
        float p3 = __expf(bs3 - mf) * invZ;
        const float winv = 1.0f / (p0 + p1 + p2 + p3 + 1e-9f);
        const int o = bh * T_LEN + tA;
        g_topi[o]  = make_int4(bi0, bi1, bi2, bi3);
        g_topw[o]  = make_float4(p0 * winv, p1 * winv, p2 * winv, p3 * winv);
        g_psink[o] = __expf(skv - mf) * invZ;
    }
}

// ================= attn2: weights via L1 (no smem staging), 128-thr CTAs =========
__global__ __launch_bounds__(128) void attn2_kernel(const float* __restrict__ vnull,
                                                    const float* __restrict__ V1w,
                                                    const float* __restrict__ V1b,
                                                    const float* __restrict__ V2b) {
    __shared__ float sV1b[256];
    __shared__ float sV2b[64];

    const int bh = blockIdx.y, b = bh / H_TOT, h = bh % H_TOT;
    const int t = blockIdx.x * 128 + threadIdx.x;

    sV1b[threadIdx.x] = V1b[threadIdx.x];
    sV1b[threadIdx.x + 128] = V1b[threadIdx.x + 128];
    if (threadIdx.x < 64) sV2b[threadIdx.x] = V2b[threadIdx.x];
    __syncthreads();

    const int o = bh * T_LEN + t;
    const int4 ti = g_topi[o];
    const float4 pw = g_topw[o];
    const float psink = g_psink[o];

    u64 mk[32];
    {
        const float4* kp0 = (const float4*)&g_kf[((size_t)bh * T_LEN + ti.x) * DH];
        const float4* kp1 = (const float4*)&g_kf[((size_t)bh * T_LEN + ti.y) * DH];
        const float4* kp2 = (const float4*)&g_kf[((size_t)bh * T_LEN + ti.z) * DH];
        const float4* kp3 = (const float4*)&g_kf[((size_t)bh * T_LEN + ti.w) * DH];
#pragma unroll
        for (int i = 0; i < 16; i++) {
            float4 a = kp0[i], c = kp1[i], e = kp2[i], f = kp3[i];
            float v0 = pw.x * a.x + pw.y * c.x + pw.z * e.x + pw.w * f.x;
            float v1 = pw.x * a.y + pw.y * c.y + pw.z * e.y + pw.w * f.y;
            float v2 = pw.x * a.z + pw.y * c.z + pw.z * e.z + pw.w * f.z;
            float v3 = pw.x * a.w + pw.y * c.w + pw.z * e.w + pw.w * f.w;
            mk[2 * i]     = f2pack(v0, v1);
            mk[2 * i + 1] = f2pack(v2, v3);
        }
    }

    u64 out2[32];
#pragma unroll
    for (int i = 0; i < 32; i++) out2[i] = *(const u64*)&sV2b[2 * i];

    for (int j = 0; j < 256; ++j) {
        const ulonglong2* v1 = (const ulonglong2*)(V1w + j * 64);   // broadcast, L1-resident
        u64 z0 = 0ull, z1 = 0ull, z2 = 0ull, z3 = 0ull;
#pragma unroll
        for (int i = 0; i < 16; i += 2) {
            ulonglong2 va = v1[i];
            ulonglong2 vb = v1[i + 1];
            z0 = f2fma(mk[2 * i],     va.x, z0);
            z1 = f2fma(mk[2 * i + 1], va.y, z1);
            z2 = f2fma(mk[2 * i + 2], vb.x, z2);
            z3 = f2fma(mk[2 * i + 3], vb.y, z3);
        }
        float z = ((f2sum(z0) + f2sum(z1)) + (f2sum(z2) + f2sum(z3))) + sV1b[j];
        float gl = 0.5f * z * (1.0f + erff(z * 0.70710678118f));
        u64 g2 = f2pack(gl, gl);
        const u64* v2 = (const u64*)(g_v2t + j * 64);               // broadcast, L1-resident
#pragma unroll
        for (int i = 0; i < 32; i++) out2[i] = f2fma(g2, v2[i], out2[i]);
    }

    const int br = h / 12, hj = h % 12;
    float* outp = &g_ctx[((size_t)(b * T_LEN + t)) * NQ + br * D_MODEL + hj * 64];
    const float* vn = vnull + h * 64;
#pragma unroll
    for (int i = 0; i < 32; i++) {
        float2 v = f2unpack(out2[i]);
        v.x = fmaf(psink, vn[2 * i], v.x);
        v.y = fmaf(psink, vn[2 * i + 1], v.y);
        ((float2*)outp)[i] = v;
    }
}

// ================= launcher =================
extern "C" void kernel_launch(void* const* d_in, const int* in_sizes, int n_in,
                              void* d_out, int out_size) {
    const float* A      = (const float*)d_in[0];
    const float* X      = (const float*)d_in[1];
    const float* WKw    = (const float*)d_in[2];
    const float* WKb    = (const float*)d_in[3];
    const float* WQw    = (const float*)d_in[4];
    const float* wedgeA = (const float*)d_in[5];
    const float* wbias  = (const float*)d_in[6];
    const float* sink   = (const float*)d_in[7];
    const float* vnull  = (const float*)d_in[8];
    const float* V1w    = (const float*)d_in[9];
    const float* V1b    = (const float*)d_in[10];
    const float* V2w    = (const float*)d_in[11];
    const float* V2b    = (const float*)d_in[12];
    const float* WOw    = (const float*)d_in[13];
    const float* WOb    = (const float*)d_in[14];
    float* Y = (float*)d_out;

    cudaFuncSetAttribute(gemm_tf32_kernel<0>, cudaFuncAttributeMaxDynamicSharedMemorySize, 51200);
    cudaFuncSetAttribute(gemm_tf32_kernel<2>, cudaFuncAttributeMaxDynamicSharedMemorySize, 51200);
    cudaFuncSetAttribute(attn1_kernel, cudaFuncAttributeMaxDynamicSharedMemorySize, 32768);

    // 1) all weight prep + rope table + V2 transpose (one launch)
    prep_w<<<3600, 256>>>(WQw, WKw, WKb, wedgeA, wbias, WOw, V2w);
    // 2) Q+K projections + rope
    gemm_tf32_kernel<0><<<dim3(48, 16, 2), 256, 51200>>>(A, X, 768);
    // 3) attention scores / softmax / top-4
    attn1_kernel<<<dim3(8, 96), 512, 32768>>>(sink);
    // 4) marker + MLP + sink   (<- ncu capture slot)
    attn2_kernel<<<dim3(8, 96), 128>>>(vnull, V1w, V1b, V2b);
    // 5) output projection, split-K over branches
    gemm_tf32_kernel<2><<<dim3(12, 16, 4), 256, 51200>>>(nullptr, nullptr, 768);
    // 6) combine partials + bias
    reduce_kernel<<<1536, 256>>>(WOb, Y);
}

// round 15
// speedup vs baseline: 1.4085x; 1.4085x over previous
#include <cuda_runtime.h>
#include <math.h>
#include <math_constants.h>

#define D_MODEL 768
#define N_BR    4
#define DH      64
#define H_TOT   48
#define BATCH   2
#define T_LEN   1024
#define M_ROWS  2048
#define NQ      3072

typedef unsigned long long u64;
typedef unsigned int u32;

// ---- packed fp32x2 helpers ----
__device__ __forceinline__ u64 f2fma(u64 a, u64 b, u64 c) {
    u64 d; asm("fma.rn.f32x2 %0, %1, %2, %3;" : "=l"(d) : "l"(a), "l"(b), "l"(c)); return d;
}
__device__ __forceinline__ u64 f2add(u64 a, u64 b) {
    u64 d; asm("add.rn.f32x2 %0, %1, %2;" : "=l"(d) : "l"(a), "l"(b)); return d;
}
__device__ __forceinline__ u64 f2pack(float lo, float hi) {
    u64 d; asm("mov.b64 %0, {%1, %2};" : "=l"(d) : "f"(lo), "f"(hi)); return d;
}
__device__ __forceinline__ float2 f2unpack(u64 a) {
    float lo, hi; asm("mov.b64 {%0, %1}, %2;" : "=f"(lo), "=f"(hi) : "l"(a)); return make_float2(lo, hi);
}
__device__ __forceinline__ float f2sum(u64 a) { float2 v = f2unpack(a); return v.x + v.y; }

// ---- tf32 split ----
__device__ __forceinline__ float2 tf32split(float x) {
    u32 hb; asm("cvt.rna.tf32.f32 %0, %1;" : "=r"(hb) : "f"(x));
    float hf = __uint_as_float(hb);
    float lo = x - hf;
    u32 lb; asm("cvt.rna.tf32.f32 %0, %1;" : "=r"(lb) : "f"(lo));
    return make_float2(hf, __uint_as_float(lb));
}

#define MMA_TF32(ACC, A0, A1, A2, A3, B0, B1)                                        \
    asm volatile("mma.sync.aligned.m16n8k8.row.col.f32.tf32.tf32.f32 "               \
                 "{%0,%1,%2,%3}, {%4,%5,%6,%7}, {%8,%9}, {%0,%1,%2,%3};"             \
                 : "+f"(ACC[0]), "+f"(ACC[1]), "+f"(ACC[2]), "+f"(ACC[3])            \
                 : "r"(A0), "r"(A1), "r"(A2), "r"(A3), "r"(B0), "r"(B1))

// ---- scratch ----
__device__ float  g_wq2f [NQ * D_MODEL];           // folded WQ
__device__ float  g_wotf [D_MODEL * NQ];           // WO as [n][br*768+c]
__device__ float  g_kbase[(size_t)M_ROWS * D_MODEL];
__device__ float  g_qf   [(size_t)M_ROWS * NQ];
__device__ float  g_kf   [(size_t)M_ROWS * NQ];
__device__ float  g_ctx  [(size_t)M_ROWS * NQ];
__device__ float  g_part [(size_t)N_BR * M_ROWS * D_MODEL];
__device__ float2 g_ropetab[T_LEN * 32];
__device__ int4   g_topi [BATCH * H_TOT * T_LEN];
__device__ float4 g_topw [BATCH * H_TOT * T_LEN];
__device__ float  g_psink[BATCH * H_TOT * T_LEN];

// ================= prep_w: WQ wedge fold + WO relayout + rope table ==============
__global__ __launch_bounds__(256) void prep_w(const float* __restrict__ WQw,
                                              const float* __restrict__ wedgeA,
                                              const float* __restrict__ wbias,
                                              const float* __restrict__ WOw) {
    __shared__ float sk[4096];
    __shared__ float Ws[64 * 68];
    __shared__ float tile[32][33];
    const int blk = blockIdx.x, tid = threadIdx.x;

    if (blk < 576) {
        const int h = blk / 12, c0 = (blk % 12) * 64;
        for (int i = tid; i < 4096; i += 256) {
            int e = i >> 6, d = i & 63;
            sk[i] = wedgeA[e * 64 + d] - wedgeA[d * 64 + e];
        }
        for (int i = tid; i < 4096; i += 256) {
            int e = i >> 6, c = i & 63;
            Ws[e * 68 + c] = WQw[(size_t)(h * 64 + e) * D_MODEL + c0 + c];
        }
        __syncthreads();
        const int d = tid >> 2, cg = (tid & 3) * 16;
        float outv[16];
        const float bd = 1.0f + wbias[h * 64 + d];
#pragma unroll
        for (int u = 0; u < 16; u++) outv[u] = bd * Ws[d * 68 + cg + u];
        for (int e = 0; e < 64; ++e) {
            float s = sk[e * 64 + d];
            const float* wr = &Ws[e * 68 + cg];
#pragma unroll
            for (int u = 0; u < 16; u++) outv[u] = fmaf(s, wr[u], outv[u]);
        }
        float* dst = g_wq2f + (size_t)(h * 64 + d) * D_MODEL + c0 + cg;
#pragma unroll
        for (int u = 0; u < 16; u++) dst[u] = outv[u];
    } else if (blk < 2880) {
        const int b3 = blk - 576;
        const int br = b3 / 576, rem = b3 % 576;
        const int cb = (rem / 24) * 32, nb = (rem % 24) * 32;
        const int tx = tid & 31, ty = tid >> 5;
        for (int r = ty; r < 32; r += 8)
            tile[r][tx] = WOw[((size_t)br * D_MODEL + cb + r) * D_MODEL + nb + tx];
        __syncthreads();
        for (int r = ty; r < 32; r += 8)
            g_wotf[(size_t)(nb + r) * NQ + br * D_MODEL + cb + tx] = tile[tx][r];
    } else {
        int idx = (blk - 2880) * 256 + tid;
        int t = idx >> 5, i = idx & 31;
        float inv = exp2f(-(float)i * 0.41524101186092034f);
        float fr = (float)t * inv;
        g_ropetab[idx] = make_float2(cosf(fr), sinf(fr));
    }
}

// ================= tf32-3x NT GEMM, double-buffered, in-loop split ===============
// MODE 0: Q proj: A0 @ g_wq2f -> rope -> g_qf    (grid 48 x 16)
// MODE 1: K base: A0 @ B1 + aux -> g_kbase       (grid 12 x 16)
// MODE 2: out proj split-K: z=br slice -> g_part (grid 12 x 16 x 4)
template <int MODE>
__global__ __launch_bounds__(256) void gemm_tf32_kernel(const float* __restrict__ A0,
                                                        const float* __restrict__ B1,
                                                        const float* __restrict__ aux,
                                                        int K) {
    extern __shared__ float2 smg[];
    float2* Abuf = smg;            // 2 x 16*132
    float2* Bbuf = smg + 4224;     // 2 x 16*68

    const int tid = threadIdx.x;
    const int m0 = blockIdx.y * 128, n0 = blockIdx.x * 64;
    const int warpId = tid >> 5, lane = tid & 31;
    const int warpM = warpId & 3, warpN = warpId >> 2;
    const int g = lane >> 2, tg = lane & 3;
    const int sa_m = tid >> 1, sa_k = (tid & 1) * 8;
    const int sb_n = tid & 63, sb_k = (tid >> 6) * 4;

    const float* Aop;
    const float* Bop;
    int ldA, ldB;
    if (MODE == 0) {
        Aop = A0; Bop = g_wq2f; ldA = 768; ldB = 768;
    } else if (MODE == 1) {
        Aop = A0; Bop = B1; ldA = 768; ldB = 768;
    } else {
        Aop = g_ctx  + blockIdx.z * 768;
        Bop = g_wotf + blockIdx.z * 768;
        ldA = 3072; ldB = 3072;
    }

    float acc[2][4][4];
#pragma unroll
    for (int mf = 0; mf < 2; mf++)
#pragma unroll
        for (int nf = 0; nf < 4; nf++)
#pragma unroll
            for (int r = 0; r < 4; r++) acc[mf][nf][r] = 0.f;

    const float* Arow = Aop + (size_t)(m0 + sa_m) * ldA + sa_k;
    const float* Brow = Bop + (size_t)(n0 + sb_n) * ldB + sb_k;

    float4 pa0 = *(const float4*)(Arow);
    float4 pa1 = *(const float4*)(Arow + 4);
    float4 pb  = *(const float4*)(Brow);

    {
        float av[8] = {pa0.x, pa0.y, pa0.z, pa0.w, pa1.x, pa1.y, pa1.z, pa1.w};
#pragma unroll
        for (int j = 0; j < 8; j++) Abuf[(sa_k + j) * 132 + sa_m] = tf32split(av[j]);
        float bv[4] = {pb.x, pb.y, pb.z, pb.w};
#pragma unroll
        for (int j = 0; j < 4; j++) Bbuf[(sb_k + j) * 68 + sb_n] = tf32split(bv[j]);
    }
    __syncthreads();

    int p = 0;
    for (int k0 = 0; k0 < K; k0 += 16) {
        const bool more = (k0 + 16) < K;
        if (more) {
            pa0 = *(const float4*)(Arow + k0 + 16);
            pa1 = *(const float4*)(Arow + k0 + 20);
            pb  = *(const float4*)(Brow + k0 + 16);
        }
        const float2* As2 = Abuf + p * 2112;
        const float2* Bs2 = Bbuf + p * 1088;
#pragma unroll
        for (int ks = 0; ks < 16; ks += 8) {
            float2 fa[2][4];
#pragma unroll
            for (int mf = 0; mf < 2; mf++) {
                const int rI = warpM * 32 + mf * 16 + g;
                const float2* c0p = &As2[(ks + tg) * 132];
                const float2* c4p = &As2[(ks + tg + 4) * 132];
                fa[mf][0] = c0p[rI];
                fa[mf][1] = c0p[rI + 8];
                fa[mf][2] = c4p[rI];
                fa[mf][3] = c4p[rI + 8];
            }
            float2 fb[4][2];
#pragma unroll
            for (int nf = 0; nf < 4; nf++) {
                const int cI = warpN * 32 + nf * 8 + g;
                fb[nf][0] = Bs2[(ks + tg) * 68 + cI];
                fb[nf][1] = Bs2[(ks + tg + 4) * 68 + cI];
            }
#pragma unroll
            for (int mf = 0; mf < 2; mf++) {
                const u32 ah0 = __float_as_uint(fa[mf][0].x), al0 = __float_as_uint(fa[mf][0].y);
                const u32 ah1 = __float_as_uint(fa[mf][1].x), al1 = __float_as_uint(fa[mf][1].y);
                const u32 ah2 = __float_as_uint(fa[mf][2].x), al2 = __float_as_uint(fa[mf][2].y);
                const u32 ah3 = __float_as_uint(fa[mf][3].x), al3 = __float_as_uint(fa[mf][3].y);
#pragma unroll
                for (int nf = 0; nf < 4; nf++) {
                    const u32 bh0 = __float_as_uint(fb[nf][0].x), bl0 = __float_as_uint(fb[nf][0].y);
                    const u32 bh1 = __float_as_uint(fb[nf][1].x), bl1 = __float_as_uint(fb[nf][1].y);
                    MMA_TF32(acc[mf][nf], al0, al1, al2, al3, bh0, bh1);
                    MMA_TF32(acc[mf][nf], ah0, ah1, ah2, ah3, bl0, bl1);
                    MMA_TF32(acc[mf][nf], ah0, ah1, ah2, ah3, bh0, bh1);
                }
            }
        }
        if (more) {
            float2* An = Abuf + (p ^ 1) * 2112;
            float2* Bn = Bbuf + (p ^ 1) * 1088;
            float av[8] = {pa0.x, pa0.y, pa0.z, pa0.w, pa1.x, pa1.y, pa1.z, pa1.w};
#pragma unroll
            for (int j = 0; j < 8; j++) An[(sa_k + j) * 132 + sa_m] = tf32split(av[j]);
            float bv[4] = {pb.x, pb.y, pb.z, pb.w};
#pragma unroll
            for (int j = 0; j < 4; j++) Bn[(sb_k + j) * 68 + sb_n] = tf32split(bv[j]);
            __syncthreads();
        }
        p ^= 1;
    }

    // ---- epilogue ----
#pragma unroll
    for (int mf = 0; mf < 2; mf++) {
#pragma unroll
        for (int nf = 0; nf < 4; nf++) {
            const int r0 = m0 + warpM * 32 + mf * 16 + g;
            const int r1 = r0 + 8;
            float c0 = acc[mf][nf][0], c1 = acc[mf][nf][1];
            float c2 = acc[mf][nf][2], c3 = acc[mf][nf][3];
            if (MODE == 0) {
                const int h = blockIdx.x;
                const int i = warpN * 16 + nf * 4 + tg;
                {
                    const int t = r0 & 1023, bb = r0 >> 10;
                    float2 rc = g_ropetab[t * 32 + i];
                    float* qp = &g_qf[(((size_t)(bb * H_TOT + h)) * T_LEN + t) * DH];
                    qp[i]      = c0 * rc.x - c1 * rc.y;
                    qp[i + 32] = c0 * rc.y + c1 * rc.x;
                }
                {
                    const int t = r1 & 1023, bb = r1 >> 10;
                    float2 rc = g_ropetab[t * 32 + i];
                    float* qp = &g_qf[(((size_t)(bb * H_TOT + h)) * T_LEN + t) * DH];
                    qp[i]      = c2 * rc.x - c3 * rc.y;
                    qp[i + 32] = c2 * rc.y + c3 * rc.x;
                }
            } else if (MODE == 1) {
                const int nc = n0 + warpN * 32 + nf * 8 + 2 * tg;
                const float b0 = aux[nc], b1 = aux[nc + 1];
                *(float2*)&g_kbase[(size_t)r0 * 768 + nc] = make_float2(c0 + b0, c1 + b1);
                *(float2*)&g_kbase[(size_t)r1 * 768 + nc] = make_float2(c2 + b0, c3 + b1);
            } else {
                const int nc = n0 + warpN * 32 + nf * 8 + 2 * tg;
                float* base = g_part + (size_t)blockIdx.z * M_ROWS * D_MODEL;
                *(float2*)&base[(size_t)r0 * 768 + nc] = make_float2(c0, c1);
                *(float2*)&base[(size_t)r1 * 768 + nc] = make_float2(c2, c3);
            }
        }
    }
}

// ================= kwr: per-head K wedge + rope (kbase -> g_kf) ==================
__global__ __launch_bounds__(128) void kwr_kernel(const float* __restrict__ wedgeA,
                                                  const float* __restrict__ wbias) {
    extern __shared__ float kwr_sm[];
    float* Ms  = kwr_sm;            // 4096
    float* kbs = kwr_sm + 4096;     // 128*65
    const int h = blockIdx.y, hj = h % 12;
    const int m0 = blockIdx.x * 128;
    const int tid = threadIdx.x;

    for (int i = tid; i < 4096; i += 128) {
        int e = i >> 6, d = i & 63;
        float v = wedgeA[e * 64 + d] - wedgeA[d * 64 + e];
        if (e == d) v += 1.0f + wbias[h * 64 + d];
        Ms[i] = v;
    }
    for (int i = tid; i < 2048; i += 128) {
        int r = i >> 4, c4 = (i & 15) * 4;
        float4 v = *(const float4*)&g_kbase[(size_t)(m0 + r) * 768 + hj * 64 + c4];
        float* dst = &kbs[r * 65 + c4];
        dst[0] = v.x; dst[1] = v.y; dst[2] = v.z; dst[3] = v.w;
    }
    __syncthreads();

    const int m = m0 + tid, b = m >> 10, t = m & 1023;
    u64 acc2[32];
#pragma unroll
    for (int i = 0; i < 32; i++) acc2[i] = 0ull;
    const float* kr = &kbs[tid * 65];
    for (int e = 0; e < 64; ++e) {
        float kv = kr[e];
        u64 kv2 = f2pack(kv, kv);
        const u64* ms = (const u64*)&Ms[e * 64];
#pragma unroll
        for (int i = 0; i < 32; i++) acc2[i] = f2fma(kv2, ms[i], acc2[i]);
    }
    float* kp = &g_kf[(((size_t)(b * H_TOT + h)) * T_LEN + t) * DH];
    const float2* rt = &g_ropetab[t * 32];
#pragma unroll
    for (int i = 0; i < 32; i++) {
        float2 w = f2unpack(acc2[i]);
        float2 rc = rt[i];
        kp[i]      = w.x * rc.x - w.y * rc.y;
        kp[i + 32] = w.x * rc.y + w.y * rc.x;
    }
}

// ================= reduce =================
__global__ __launch_bounds__(256) void reduce_kernel(const float* __restrict__ WOb,
                                                     float* __restrict__ Y) {
    const size_t i4 = (size_t)blockIdx.x * 256 + threadIdx.x;
    const size_t base = i4 * 4;
    const int nc = (int)(base % 768);
    float4 p0 = *(const float4*)&g_part[base];
    float4 p1 = *(const float4*)&g_part[base + (size_t)M_ROWS * D_MODEL];
    float4 p2 = *(const float4*)&g_part[base + (size_t)2 * M_ROWS * D_MODEL];
    float4 p3 = *(const float4*)&g_part[base + (size_t)3 * M_ROWS * D_MODEL];
    float4 o;
    o.x = 0.25f * (p0.x + p1.x + p2.x + p3.x) + 0.25f * (WOb[nc]     + WOb[768 + nc]     + WOb[1536 + nc]     + WOb[2304 + nc]);
    o.y = 0.25f * (p0.y + p1.y + p2.y + p3.y) + 0.25f * (WOb[nc + 1] + WOb[768 + nc + 1] + WOb[1536 + nc + 1] + WOb[2304 + nc + 1]);
    o.z = 0.25f * (p0.z + p1.z + p2.z + p3.z) + 0.25f * (WOb[nc + 2] + WOb[768 + nc + 2] + WOb[1536 + nc + 2] + WOb[2304 + nc + 2]);
    o.w = 0.25f * (p0.w + p1.w + p2.w + p3.w) + 0.25f * (WOb[nc + 3] + WOb[768 + nc + 3] + WOb[1536 + nc + 3] + WOb[2304 + nc + 3]);
    *(float4*)&Y[base] = o;
}

// ---- online softmax + top-4 update ----
#define SMTK_UPDATE(sc, sidx, mrun, lrun, s0v, s1v, s2v, s3v, i0v, i1v, i2v, i3v) \
    do {                                                                          \
        if ((sc) <= (mrun)) { (lrun) += __expf((sc) - (mrun)); }                  \
        else { (lrun) = fmaf((lrun), __expf((mrun) - (sc)), 1.0f); (mrun) = (sc); } \
        if ((sc) > (s3v)) {                                                       \
            if ((sc) > (s2v)) {                                                   \
                (s3v) = (s2v); (i3v) = (i2v);                                     \
                if ((sc) > (s1v)) {                                               \
                    (s2v) = (s1v); (i2v) = (i1v);                                 \
                    if ((sc) > (s0v)) {                                           \
                        (s1v) = (s0v); (i1v) = (i0v);                             \
                        (s0v) = (sc); (i0v) = (sidx);                             \
                    } else { (s1v) = (sc); (i1v) = (sidx); }                      \
                } else { (s2v) = (sc); (i2v) = (sidx); }                          \
            } else { (s3v) = (sc); (i3v) = (sidx); }                              \
        }                                                                         \
    } while (0)

#define MERGE_INS(sc, ix)                                                         \
    do {                                                                          \
        if ((sc) > bs3 || ((sc) == bs3 && (ix) < bi3)) {                          \
            if ((sc) > bs2 || ((sc) == bs2 && (ix) < bi2)) {                      \
                bs3 = bs2; bi3 = bi2;                                             \
                if ((sc) > bs1 || ((sc) == bs1 && (ix) < bi1)) {                  \
                    bs2 = bs1; bi2 = bi1;                                         \
                    if ((sc) > bs0 || ((sc) == bs0 && (ix) < bi0)) {              \
                        bs1 = bs0; bi1 = bi0; bs0 = (sc); bi0 = (ix);             \
                    } else { bs1 = (sc); bi1 = (ix); }                            \
                } else { bs2 = (sc); bi2 = (ix); }                                \
            } else { bs3 = (sc); bi3 = (ix); }                                    \
        }                                                                         \
    } while (0)

// ================= attn1: R11 form (4-way s-phase split, LDS.128 k reads) ========
__global__ __launch_bounds__(512) void attn1_kernel(const float* __restrict__ sink) {
    extern __shared__ float ks[];            // 8192 floats
    const int bh = blockIdx.y, h = bh % H_TOT;
    const int xt = (gridDim.x - 1) - blockIdx.x;
    const int t0 = xt * 128;
    const int tid = threadIdx.x;
    const int ph  = tid >> 7;                // 0..3
    const int tA = t0 + (tid & 127);

    u64 q2[32];
    {
        const ulonglong2* qp = (const ulonglong2*)&g_qf[((size_t)bh * T_LEN + tA) * DH];
#pragma unroll
        for (int i = 0; i < 16; i++) { ulonglong2 v = qp[i]; q2[2 * i] = v.x; q2[2 * i + 1] = v.y; }
    }

    float mrun = -CUDART_INF_F, lrun = 0.f;
    float ts0 = -CUDART_INF_F, ts1 = -CUDART_INF_F, ts2 = -CUDART_INF_F, ts3 = -CUDART_INF_F;
    int ti0 = 0, ti1 = 0, ti2 = 0, ti3 = 0;

    for (int s0 = 0; s0 <= t0; s0 += 128) {
        __syncthreads();
        {
            const float4* kg = (const float4*)&g_kf[((size_t)bh * T_LEN + s0) * DH];
            float4* d4 = (float4*)ks;
#pragma unroll
            for (int j = 0; j < 4; j++) d4[tid + j * 512] = kg[tid + j * 512];
        }
        __syncthreads();

        const int sMax = min(tA, s0 + 127);
        for (int s = s0 + ph; s <= sMax; s += 4) {
            const ulonglong2* kr = (const ulonglong2*)(ks + (s - s0) * DH);
            u64 a0 = 0ull, a1 = 0ull, a2 = 0ull, a3 = 0ull;
#pragma unroll
            for (int i = 0; i < 16; i += 4) {
                ulonglong2 k01 = kr[i];
                ulonglong2 k23 = kr[i + 1];
                ulonglong2 k45 = kr[i + 2];
                ulonglong2 k67 = kr[i + 3];
                a0 = f2fma(q2[2 * i],     k01.x, a0);
                a1 = f2fma(q2[2 * i + 1], k01.y, a1);
                a2 = f2fma(q2[2 * i + 2], k23.x, a2);
                a3 = f2fma(q2[2 * i + 3], k23.y, a3);
                a0 = f2fma(q2[2 * i + 4], k45.x, a0);
                a1 = f2fma(q2[2 * i + 5], k45.y, a1);
                a2 = f2fma(q2[2 * i + 6], k67.x, a2);
                a3 = f2fma(q2[2 * i + 7], k67.y, a3);
            }
            u64 s01 = f2add(a0, a1);
            u64 s23 = f2add(a2, a3);
            float2 sv = f2unpack(f2add(s01, s23));
            float sc = (sv.x + sv.y) * 0.125f;
            SMTK_UPDATE(sc, s, mrun, lrun, ts0, ts1, ts2, ts3, ti0, ti1, ti2, ti3);
        }
    }

    // ---- merge 4 phases per row ----
    __syncthreads();
    float* Pm = ks;
    float* Pl = ks + 512;
    float* Ps = ks + 1024;
    int*   Pi = (int*)(ks + 3072);
    Pm[tid] = mrun; Pl[tid] = lrun;
    Ps[tid * 4 + 0] = ts0; Ps[tid * 4 + 1] = ts1; Ps[tid * 4 + 2] = ts2; Ps[tid * 4 + 3] = ts3;
    Pi[tid * 4 + 0] = ti0; Pi[tid * 4 + 1] = ti1; Pi[tid * 4 + 2] = ti2; Pi[tid * 4 + 3] = ti3;
    __syncthreads();

    if (tid < 128) {
        float m0v = Pm[tid], m1v = Pm[tid + 128], m2v = Pm[tid + 256], m3v = Pm[tid + 384];
        float mm = fmaxf(fmaxf(m0v, m1v), fmaxf(m2v, m3v));
        float ll = Pl[tid]       * __expf(m0v - mm)
                 + Pl[tid + 128] * __expf(m1v - mm)
                 + Pl[tid + 256] * __expf(m2v - mm)
                 + Pl[tid + 384] * __expf(m3v - mm);

        float bs0 = -CUDART_INF_F, bs1 = -CUDART_INF_F, bs2 = -CUDART_INF_F, bs3 = -CUDART_INF_F;
        int bi0 = 0x7fffffff, bi1 = 0x7fffffff, bi2 = 0x7fffffff, bi3 = 0x7fffffff;
#pragma unroll
        for (int pp = 0; pp < 4; pp++) {
            const int pidx = pp * 128 + tid;
#pragma unroll
            for (int j = 0; j < 4; j++) {
                float sc = Ps[pidx * 4 + j];
                int   ix = Pi[pidx * 4 + j];
                MERGE_INS(sc, ix);
            }
        }
        if (bi0 == 0x7fffffff) bi0 = 0;
        if (bi1 == 0x7fffffff) bi1 = 0;
        if (bi2 == 0x7fffffff) bi2 = 0;
        if (bi3 == 0x7fffffff) bi3 = 0;

        const float skv = sink[h];
        const float mf = fmaxf(mm, skv);
        const float Z = ll * __expf(mm - mf) + __expf(skv - mf);
        const float invZ = 1.0f / Z;
        float p0 = __expf(bs0 - mf) * invZ;
        float p1 = __expf(bs1 - mf) * invZ;
        float p2 = __expf(bs2 - mf) * invZ;
        float p3 = __expf(bs3 - mf) * invZ;
        const float winv = 1.0f / (p0 + p1 + p2 + p3 + 1e-9f);
        const int o = bh * T_LEN + t0 + tid;
        g_topi[o]  = make_int4(bi0, bi1, bi2, bi3);
        g_topw[o]  = make_float4(p0 * winv, p1 * winv, p2 * winv, p3 * winv);
        g_psink[o] = __expf(skv - mf) * invZ;
    }
}

// ================= attn2: R11 smem form (256 thr, V1+V2t staged) =================
__global__ __launch_bounds__(256) void attn2_kernel(const float* __restrict__ vnull,
                                                    const float* __restrict__ V1w,
                                                    const float* __restrict__ V1b,
                                                    const float* __restrict__ V2w,
                                                    const float* __restrict__ V2b) {
    extern __shared__ float sm2[];
    float* V1s = sm2;                 // 16384
    float* V2t = sm2 + 16384;         // 256*66
    __shared__ float sV1b[256];
    __shared__ float sV2b[64];

    const int bh = blockIdx.y, b = bh / H_TOT, h = bh % H_TOT;
    const int t = blockIdx.x * 256 + threadIdx.x;

    for (int i = threadIdx.x; i < 4096; i += 256) ((float4*)V1s)[i] = ((const float4*)V1w)[i];
    for (int i = threadIdx.x; i < 16384; i += 256) {
        int dd = i >> 8, j = i & 255;
        V2t[j * 66 + dd] = V2w[i];
    }
    if (threadIdx.x < 256) sV1b[threadIdx.x] = V1b[threadIdx.x];
    if (threadIdx.x < 64)  sV2b[threadIdx.x] = V2b[threadIdx.x];
    __syncthreads();

    const int o = bh * T_LEN + t;
    const int4 ti = g_topi[o];
    const float4 pw = g_topw[o];
    const float psink = g_psink[o];

    u64 mk[32];
    {
        const float4* kp0 = (const float4*)&g_kf[((size_t)bh * T_LEN + ti.x) * DH];
        const float4* kp1 = (const float4*)&g_kf[((size_t)bh * T_LEN + ti.y) * DH];
        const float4* kp2 = (const float4*)&g_kf[((size_t)bh * T_LEN + ti.z) * DH];
        const float4* kp3 = (const float4*)&g_kf[((size_t)bh * T_LEN + ti.w) * DH];
#pragma unroll
        for (int i = 0; i < 16; i++) {
            float4 a = kp0[i], c = kp1[i], e = kp2[i], f = kp3[i];
            float v0 = pw.x * a.x + pw.y * c.x + pw.z * e.x + pw.w * f.x;
            float v1 = pw.x * a.y + pw.y * c.y + pw.z * e.y + pw.w * f.y;
            float v2 = pw.x * a.z + pw.y * c.z + pw.z * e.z + pw.w * f.z;
            float v3 = pw.x * a.w + pw.y * c.w + pw.z * e.w + pw.w * f.w;
            mk[2 * i]     = f2pack(v0, v1);
            mk[2 * i + 1] = f2pack(v2, v3);
        }
    }

    u64 out2[32];
#pragma unroll
    for (int i = 0; i < 32; i++) out2[i] = *(const u64*)&sV2b[2 * i];

    for (int j = 0; j < 256; ++j) {
        const ulonglong2* v1 = (const ulonglong2*)(V1s + j * 64);
        u64 z0 = 0ull, z1 = 0ull, z2 = 0ull, z3 = 0ull;
#pragma unroll
        for (int i = 0; i < 16; i += 2) {
            ulonglong2 va = v1[i];
            ulonglong2 vb = v1[i + 1];
            z0 = f2fma(mk[2 * i],     va.x, z0);
            z1 = f2fma(mk[2 * i + 1], va.y, z1);
            z2 = f2fma(mk[2 * i + 2], vb.x, z2);
            z3 = f2fma(mk[2 * i + 3], vb.y, z3);
        }
        float z = ((f2sum(z0) + f2sum(z1)) + (f2sum(z2) + f2sum(z3))) + sV1b[j];
        float gl = 0.5f * z * (1.0f + erff(z * 0.70710678118f));
        u64 g2 = f2pack(gl, gl);
        const u64* v2 = (const u64*)(V2t + j * 66);
#pragma unroll
        for (int i = 0; i < 32; i++) out2[i] = f2fma(g2, v2[i], out2[i]);
    }

    const int br = h / 12, hj = h % 12;
    float* outp = &g_ctx[((size_t)(b * T_LEN + t)) * NQ + br * D_MODEL + hj * 64];
    const float* vn = vnull + h * 64;
#pragma unroll
    for (int i = 0; i < 32; i++) {
        float2 v = f2unpack(out2[i]);
        v.x = fmaf(psink, vn[2 * i], v.x);
        v.y = fmaf(psink, vn[2 * i + 1], v.y);
        ((float2*)outp)[i] = v;
    }
}

// ================= launcher =================
extern "C" void kernel_launch(void* const* d_in, const int* in_sizes, int n_in,
                              void* d_out, int out_size) {
    const float* A      = (const float*)d_in[0];
    const float* X      = (const float*)d_in[1];
    const float* WKw    = (const float*)d_in[2];
    const float* WKb    = (const float*)d_in[3];
    const float* WQw    = (const float*)d_in[4];
    const float* wedgeA = (const float*)d_in[5];
    const float* wbias  = (const float*)d_in[6];
    const float* sink   = (const float*)d_in[7];
    const float* vnull  = (const float*)d_in[8];
    const float* V1w    = (const float*)d_in[9];
    const float* V1b    = (const float*)d_in[10];
    const float* V2w    = (const float*)d_in[11];
    const float* V2b    = (const float*)d_in[12];
    const float* WOw    = (const float*)d_in[13];
    const float* WOb    = (const float*)d_in[14];
    float* Y = (float*)d_out;

    cudaFuncSetAttribute(gemm_tf32_kernel<0>, cudaFuncAttributeMaxDynamicSharedMemorySize, 51200);
    cudaFuncSetAttribute(gemm_tf32_kernel<1>, cudaFuncAttributeMaxDynamicSharedMemorySize, 51200);
    cudaFuncSetAttribute(gemm_tf32_kernel<2>, cudaFuncAttributeMaxDynamicSharedMemorySize, 51200);
    cudaFuncSetAttribute(attn1_kernel, cudaFuncAttributeMaxDynamicSharedMemorySize, 32768);
    cudaFuncSetAttribute(attn2_kernel, cudaFuncAttributeMaxDynamicSharedMemorySize, 133120);
    cudaFuncSetAttribute(kwr_kernel,   cudaFuncAttributeMaxDynamicSharedMemorySize, 50176);

    // 1) WQ fold + WO relayout + rope table
    prep_w<<<3008, 256>>>(WQw, wedgeA, wbias, WOw);
    // 2) K base projection (12 heads)
    gemm_tf32_kernel<1><<<dim3(12, 16), 256, 51200>>>(X, WKw, WKb, 768);
    // 3) K wedge + rope (48 head variants)
    kwr_kernel<<<dim3(16, 48), 128, 50176>>>(wedgeA, wbias);
    // 4) Q projection + rope   (<- ncu capture slot)
    gemm_tf32_kernel<0><<<dim3(48, 16), 256, 51200>>>(A, nullptr, nullptr, 768);
    // 5) attention scores / softmax / top-4
    attn1_kernel<<<dim3(8, 96), 512, 32768>>>(sink);
    // 6) marker + MLP + sink
    attn2_kernel<<<dim3(4, 96), 256, 133120>>>(vnull, V1w, V1b, V2w, V2b);
    // 7) output projection, split-K over branches
    gemm_tf32_kernel<2><<<dim3(12, 16, 4), 256, 51200>>>(nullptr, nullptr, nullptr, 768);
    // 8) combine partials + bias
    reduce_kernel<<<1536, 256>>>(WOb, Y);
}

// round 16
// speedup vs baseline: 1.4398x; 1.0222x over previous
#include <cuda_runtime.h>
#include <math.h>
#include <math_constants.h>

#define D_MODEL 768
#define N_BR    4
#define DH      64
#define H_TOT   48
#define BATCH   2
#define T_LEN   1024
#define M_ROWS  2048
#define NQ      3072

typedef unsigned long long u64;
typedef unsigned int u32;

// ---- packed fp32x2 helpers ----
__device__ __forceinline__ u64 f2fma(u64 a, u64 b, u64 c) {
    u64 d; asm("fma.rn.f32x2 %0, %1, %2, %3;" : "=l"(d) : "l"(a), "l"(b), "l"(c)); return d;
}
__device__ __forceinline__ u64 f2add(u64 a, u64 b) {
    u64 d; asm("add.rn.f32x2 %0, %1, %2;" : "=l"(d) : "l"(a), "l"(b)); return d;
}
__device__ __forceinline__ u64 f2pack(float lo, float hi) {
    u64 d; asm("mov.b64 %0, {%1, %2};" : "=l"(d) : "f"(lo), "f"(hi)); return d;
}
__device__ __forceinline__ float2 f2unpack(u64 a) {
    float lo, hi; asm("mov.b64 {%0, %1}, %2;" : "=f"(lo), "=f"(hi) : "l"(a)); return make_float2(lo, hi);
}
__device__ __forceinline__ float f2sum(u64 a) { float2 v = f2unpack(a); return v.x + v.y; }

// ---- tf32 split ----
__device__ __forceinline__ float2 tf32split(float x) {
    u32 hb; asm("cvt.rna.tf32.f32 %0, %1;" : "=r"(hb) : "f"(x));
    float hf = __uint_as_float(hb);
    float lo = x - hf;
    u32 lb; asm("cvt.rna.tf32.f32 %0, %1;" : "=r"(lb) : "f"(lo));
    return make_float2(hf, __uint_as_float(lb));
}

#define MMA_TF32(ACC, A0, A1, A2, A3, B0, B1)                                        \
    asm volatile("mma.sync.aligned.m16n8k8.row.col.f32.tf32.tf32.f32 "               \
                 "{%0,%1,%2,%3}, {%4,%5,%6,%7}, {%8,%9}, {%0,%1,%2,%3};"             \
                 : "+f"(ACC[0]), "+f"(ACC[1]), "+f"(ACC[2]), "+f"(ACC[3])            \
                 : "r"(A0), "r"(A1), "r"(A2), "r"(A3), "r"(B0), "r"(B1))

// ---- scratch ----
__device__ float  g_wq2f [NQ * D_MODEL];           // folded WQ
__device__ float  g_wotf [D_MODEL * NQ];           // WO as [n][br*768+c]
__device__ float  g_kbase[(size_t)M_ROWS * D_MODEL];
__device__ float  g_qf   [(size_t)M_ROWS * NQ];
__device__ float  g_kf   [(size_t)M_ROWS * NQ];
__device__ float  g_ctx  [(size_t)M_ROWS * NQ];
__device__ float  g_part [(size_t)N_BR * M_ROWS * D_MODEL];
__device__ float2 g_ropetab[T_LEN * 32];
__device__ int4   g_topi [BATCH * H_TOT * T_LEN];
__device__ float4 g_topw [BATCH * H_TOT * T_LEN];
__device__ float  g_psink[BATCH * H_TOT * T_LEN];

// ================= prep_w: WQ wedge fold + WO relayout + rope table ==============
__global__ __launch_bounds__(256) void prep_w(const float* __restrict__ WQw,
                                              const float* __restrict__ wedgeA,
                                              const float* __restrict__ wbias,
                                              const float* __restrict__ WOw) {
    __shared__ float sk[4096];
    __shared__ float Ws[64 * 68];
    __shared__ float tile[32][33];
    const int blk = blockIdx.x, tid = threadIdx.x;

    if (blk < 576) {
        const int h = blk / 12, c0 = (blk % 12) * 64;
        for (int i = tid; i < 4096; i += 256) {
            int e = i >> 6, d = i & 63;
            sk[i] = wedgeA[e * 64 + d] - wedgeA[d * 64 + e];
        }
        for (int i = tid; i < 4096; i += 256) {
            int e = i >> 6, c = i & 63;
            Ws[e * 68 + c] = WQw[(size_t)(h * 64 + e) * D_MODEL + c0 + c];
        }
        __syncthreads();
        const int d = tid >> 2, cg = (tid & 3) * 16;
        float outv[16];
        const float bd = 1.0f + wbias[h * 64 + d];
#pragma unroll
        for (int u = 0; u < 16; u++) outv[u] = bd * Ws[d * 68 + cg + u];
        for (int e = 0; e < 64; ++e) {
            float s = sk[e * 64 + d];
            const float* wr = &Ws[e * 68 + cg];
#pragma unroll
            for (int u = 0; u < 16; u++) outv[u] = fmaf(s, wr[u], outv[u]);
        }
        float* dst = g_wq2f + (size_t)(h * 64 + d) * D_MODEL + c0 + cg;
#pragma unroll
        for (int u = 0; u < 16; u++) dst[u] = outv[u];
    } else if (blk < 2880) {
        const int b3 = blk - 576;
        const int br = b3 / 576, rem = b3 % 576;
        const int cb = (rem / 24) * 32, nb = (rem % 24) * 32;
        const int tx = tid & 31, ty = tid >> 5;
        for (int r = ty; r < 32; r += 8)
            tile[r][tx] = WOw[((size_t)br * D_MODEL + cb + r) * D_MODEL + nb + tx];
        __syncthreads();
        for (int r = ty; r < 32; r += 8)
            g_wotf[(size_t)(nb + r) * NQ + br * D_MODEL + cb + tx] = tile[tx][r];
    } else {
        int idx = (blk - 2880) * 256 + tid;
        int t = idx >> 5, i = idx & 31;
        float inv = exp2f(-(float)i * 0.41524101186092034f);
        float fr = (float)t * inv;
        g_ropetab[idx] = make_float2(cosf(fr), sinf(fr));
    }
}

// ================= tf32-3x NT GEMM, double-buffered, in-loop split ===============
// MODE 0 (fused QK): bx<48: Q proj head bx -> rope -> g_qf
//                    bx>=48: K base n-tile (bx-48) -> +bias -> g_kbase
// MODE 2: out proj split-K: z=br slice -> g_part
template <int MODE>
__global__ __launch_bounds__(256) void gemm_tf32_kernel(const float* __restrict__ A0,
                                                        const float* __restrict__ A1,
                                                        const float* __restrict__ B1,
                                                        const float* __restrict__ aux,
                                                        int K) {
    extern __shared__ float2 smg[];
    float2* Abuf = smg;            // 2 x 16*132
    float2* Bbuf = smg + 4224;     // 2 x 16*68

    const int tid = threadIdx.x;
    const int m0 = blockIdx.y * 128;
    const int warpId = tid >> 5, lane = tid & 31;
    const int warpM = warpId & 3, warpN = warpId >> 2;
    const int g = lane >> 2, tg = lane & 3;
    const int sa_m = tid >> 1, sa_k = (tid & 1) * 8;
    const int sb_n = tid & 63, sb_k = (tid >> 6) * 4;

    const float* Aop;
    const float* Bop;
    int ldA, ldB, n0;
    bool isQ = true;
    if (MODE == 0) {
        isQ = blockIdx.x < 48;
        n0 = (isQ ? blockIdx.x : (blockIdx.x - 48)) * 64;
        Aop = isQ ? A0 : A1;
        Bop = isQ ? g_wq2f : B1;
        ldA = 768; ldB = 768;
    } else {
        n0 = blockIdx.x * 64;
        Aop = g_ctx  + blockIdx.z * 768;
        Bop = g_wotf + blockIdx.z * 768;
        ldA = 3072; ldB = 3072;
    }

    float acc[2][4][4];
#pragma unroll
    for (int mf = 0; mf < 2; mf++)
#pragma unroll
        for (int nf = 0; nf < 4; nf++)
#pragma unroll
            for (int r = 0; r < 4; r++) acc[mf][nf][r] = 0.f;

    const float* Arow = Aop + (size_t)(m0 + sa_m) * ldA + sa_k;
    const float* Brow = Bop + (size_t)(n0 + sb_n) * ldB + sb_k;

    float4 pa0 = *(const float4*)(Arow);
    float4 pa1 = *(const float4*)(Arow + 4);
    float4 pb  = *(const float4*)(Brow);

    {
        float av[8] = {pa0.x, pa0.y, pa0.z, pa0.w, pa1.x, pa1.y, pa1.z, pa1.w};
#pragma unroll
        for (int j = 0; j < 8; j++) Abuf[(sa_k + j) * 132 + sa_m] = tf32split(av[j]);
        float bv[4] = {pb.x, pb.y, pb.z, pb.w};
#pragma unroll
        for (int j = 0; j < 4; j++) Bbuf[(sb_k + j) * 68 + sb_n] = tf32split(bv[j]);
    }
    __syncthreads();

    int p = 0;
    for (int k0 = 0; k0 < K; k0 += 16) {
        const bool more = (k0 + 16) < K;
        if (more) {
            pa0 = *(const float4*)(Arow + k0 + 16);
            pa1 = *(const float4*)(Arow + k0 + 20);
            pb  = *(const float4*)(Brow + k0 + 16);
        }
        const float2* As2 = Abuf + p * 2112;
        const float2* Bs2 = Bbuf + p * 1088;
#pragma unroll
        for (int ks = 0; ks < 16; ks += 8) {
            float2 fa[2][4];
#pragma unroll
            for (int mf = 0; mf < 2; mf++) {
                const int rI = warpM * 32 + mf * 16 + g;
                const float2* c0p = &As2[(ks + tg) * 132];
                const float2* c4p = &As2[(ks + tg + 4) * 132];
                fa[mf][0] = c0p[rI];
                fa[mf][1] = c0p[rI + 8];
                fa[mf][2] = c4p[rI];
                fa[mf][3] = c4p[rI + 8];
            }
            float2 fb[4][2];
#pragma unroll
            for (int nf = 0; nf < 4; nf++) {
                const int cI = warpN * 32 + nf * 8 + g;
                fb[nf][0] = Bs2[(ks + tg) * 68 + cI];
                fb[nf][1] = Bs2[(ks + tg + 4) * 68 + cI];
            }
#pragma unroll
            for (int mf = 0; mf < 2; mf++) {
                const u32 ah0 = __float_as_uint(fa[mf][0].x), al0 = __float_as_uint(fa[mf][0].y);
                const u32 ah1 = __float_as_uint(fa[mf][1].x), al1 = __float_as_uint(fa[mf][1].y);
                const u32 ah2 = __float_as_uint(fa[mf][2].x), al2 = __float_as_uint(fa[mf][2].y);
                const u32 ah3 = __float_as_uint(fa[mf][3].x), al3 = __float_as_uint(fa[mf][3].y);
#pragma unroll
                for (int nf = 0; nf < 4; nf++) {
                    const u32 bh0 = __float_as_uint(fb[nf][0].x), bl0 = __float_as_uint(fb[nf][0].y);
                    const u32 bh1 = __float_as_uint(fb[nf][1].x), bl1 = __float_as_uint(fb[nf][1].y);
                    MMA_TF32(acc[mf][nf], al0, al1, al2, al3, bh0, bh1);
                    MMA_TF32(acc[mf][nf], ah0, ah1, ah2, ah3, bl0, bl1);
                    MMA_TF32(acc[mf][nf], ah0, ah1, ah2, ah3, bh0, bh1);
                }
            }
        }
        if (more) {
            float2* An = Abuf + (p ^ 1) * 2112;
            float2* Bn = Bbuf + (p ^ 1) * 1088;
            float av[8] = {pa0.x, pa0.y, pa0.z, pa0.w, pa1.x, pa1.y, pa1.z, pa1.w};
#pragma unroll
            for (int j = 0; j < 8; j++) An[(sa_k + j) * 132 + sa_m] = tf32split(av[j]);
            float bv[4] = {pb.x, pb.y, pb.z, pb.w};
#pragma unroll
            for (int j = 0; j < 4; j++) Bn[(sb_k + j) * 68 + sb_n] = tf32split(bv[j]);
            __syncthreads();
        }
        p ^= 1;
    }

    // ---- epilogue ----
#pragma unroll
    for (int mf = 0; mf < 2; mf++) {
#pragma unroll
        for (int nf = 0; nf < 4; nf++) {
            const int r0 = m0 + warpM * 32 + mf * 16 + g;
            const int r1 = r0 + 8;
            float c0 = acc[mf][nf][0], c1 = acc[mf][nf][1];
            float c2 = acc[mf][nf][2], c3 = acc[mf][nf][3];
            if (MODE == 0) {
                if (isQ) {
                    const int h = blockIdx.x;
                    const int i = warpN * 16 + nf * 4 + tg;
                    {
                        const int t = r0 & 1023, bb = r0 >> 10;
                        float2 rc = g_ropetab[t * 32 + i];
                        float* qp = &g_qf[(((size_t)(bb * H_TOT + h)) * T_LEN + t) * DH];
                        qp[i]      = c0 * rc.x - c1 * rc.y;
                        qp[i + 32] = c0 * rc.y + c1 * rc.x;
                    }
                    {
                        const int t = r1 & 1023, bb = r1 >> 10;
                        float2 rc = g_ropetab[t * 32 + i];
                        float* qp = &g_qf[(((size_t)(bb * H_TOT + h)) * T_LEN + t) * DH];
                        qp[i]      = c2 * rc.x - c3 * rc.y;
                        qp[i + 32] = c2 * rc.y + c3 * rc.x;
                    }
                } else {
                    const int nc = n0 + warpN * 32 + nf * 8 + 2 * tg;
                    const float b0 = aux[nc], b1 = aux[nc + 1];
                    *(float2*)&g_kbase[(size_t)r0 * 768 + nc] = make_float2(c0 + b0, c1 + b1);
                    *(float2*)&g_kbase[(size_t)r1 * 768 + nc] = make_float2(c2 + b0, c3 + b1);
                }
            } else {
                const int nc = n0 + warpN * 32 + nf * 8 + 2 * tg;
                float* base = g_part + (size_t)blockIdx.z * M_ROWS * D_MODEL;
                *(float2*)&base[(size_t)r0 * 768 + nc] = make_float2(c0, c1);
                *(float2*)&base[(size_t)r1 * 768 + nc] = make_float2(c2, c3);
            }
        }
    }
}

// ================= kwr: per-head K wedge + rope (kbase -> g_kf) ==================
__global__ __launch_bounds__(128) void kwr_kernel(const float* __restrict__ wedgeA,
                                                  const float* __restrict__ wbias) {
    extern __shared__ float kwr_sm[];
    float* Ms  = kwr_sm;            // 4096
    float* kbs = kwr_sm + 4096;     // 128*65
    const int h = blockIdx.y, hj = h % 12;
    const int m0 = blockIdx.x * 128;
    const int tid = threadIdx.x;

    for (int i = tid; i < 4096; i += 128) {
        int e = i >> 6, d = i & 63;
        float v = wedgeA[e * 64 + d] - wedgeA[d * 64 + e];
        if (e == d) v += 1.0f + wbias[h * 64 + d];
        Ms[i] = v;
    }
    for (int i = tid; i < 2048; i += 128) {
        int r = i >> 4, c4 = (i & 15) * 4;
        float4 v = *(const float4*)&g_kbase[(size_t)(m0 + r) * 768 + hj * 64 + c4];
        float* dst = &kbs[r * 65 + c4];
        dst[0] = v.x; dst[1] = v.y; dst[2] = v.z; dst[3] = v.w;
    }
    __syncthreads();

    const int m = m0 + tid, b = m >> 10, t = m & 1023;
    u64 acc2[32];
#pragma unroll
    for (int i = 0; i < 32; i++) acc2[i] = 0ull;
    const float* kr = &kbs[tid * 65];
    for (int e = 0; e < 64; ++e) {
        float kv = kr[e];
        u64 kv2 = f2pack(kv, kv);
        const u64* ms = (const u64*)&Ms[e * 64];
#pragma unroll
        for (int i = 0; i < 32; i++) acc2[i] = f2fma(kv2, ms[i], acc2[i]);
    }
    float* kp = &g_kf[(((size_t)(b * H_TOT + h)) * T_LEN + t) * DH];
    const float2* rt = &g_ropetab[t * 32];
#pragma unroll
    for (int i = 0; i < 32; i++) {
        float2 w = f2unpack(acc2[i]);
        float2 rc = rt[i];
        kp[i]      = w.x * rc.x - w.y * rc.y;
        kp[i + 32] = w.x * rc.y + w.y * rc.x;
    }
}

// ================= reduce =================
__global__ __launch_bounds__(256) void reduce_kernel(const float* __restrict__ WOb,
                                                     float* __restrict__ Y) {
    const size_t i4 = (size_t)blockIdx.x * 256 + threadIdx.x;
    const size_t base = i4 * 4;
    const int nc = (int)(base % 768);
    float4 p0 = *(const float4*)&g_part[base];
    float4 p1 = *(const float4*)&g_part[base + (size_t)M_ROWS * D_MODEL];
    float4 p2 = *(const float4*)&g_part[base + (size_t)2 * M_ROWS * D_MODEL];
    float4 p3 = *(const float4*)&g_part[base + (size_t)3 * M_ROWS * D_MODEL];
    float4 o;
    o.x = 0.25f * (p0.x + p1.x + p2.x + p3.x) + 0.25f * (WOb[nc]     + WOb[768 + nc]     + WOb[1536 + nc]     + WOb[2304 + nc]);
    o.y = 0.25f * (p0.y + p1.y + p2.y + p3.y) + 0.25f * (WOb[nc + 1] + WOb[768 + nc + 1] + WOb[1536 + nc + 1] + WOb[2304 + nc + 1]);
    o.z = 0.25f * (p0.z + p1.z + p2.z + p3.z) + 0.25f * (WOb[nc + 2] + WOb[768 + nc + 2] + WOb[1536 + nc + 2] + WOb[2304 + nc + 2]);
    o.w = 0.25f * (p0.w + p1.w + p2.w + p3.w) + 0.25f * (WOb[nc + 3] + WOb[768 + nc + 3] + WOb[1536 + nc + 3] + WOb[2304 + nc + 3]);
    *(float4*)&Y[base] = o;
}

// ---- online softmax + top-4 update ----
#define SMTK_UPDATE(sc, sidx, mrun, lrun, s0v, s1v, s2v, s3v, i0v, i1v, i2v, i3v) \
    do {                                                                          \
        if ((sc) <= (mrun)) { (lrun) += __expf((sc) - (mrun)); }                  \
        else { (lrun) = fmaf((lrun), __expf((mrun) - (sc)), 1.0f); (mrun) = (sc); } \
        if ((sc) > (s3v)) {                                                       \
            if ((sc) > (s2v)) {                                                   \
                (s3v) = (s2v); (i3v) = (i2v);                                     \
                if ((sc) > (s1v)) {                                               \
                    (s2v) = (s1v); (i2v) = (i1v);                                 \
                    if ((sc) > (s0v)) {                                           \
                        (s1v) = (s0v); (i1v) = (i0v);                             \
                        (s0v) = (sc); (i0v) = (sidx);                             \
                    } else { (s1v) = (sc); (i1v) = (sidx); }                      \
                } else { (s2v) = (sc); (i2v) = (sidx); }                          \
            } else { (s3v) = (sc); (i3v) = (sidx); }                              \
        }                                                                         \
    } while (0)

#define MERGE_INS(sc, ix)                                                         \
    do {                                                                          \
        if ((sc) > bs3 || ((sc) == bs3 && (ix) < bi3)) {                          \
            if ((sc) > bs2 || ((sc) == bs2 && (ix) < bi2)) {                      \
                bs3 = bs2; bi3 = bi2;                                             \
                if ((sc) > bs1 || ((sc) == bs1 && (ix) < bi1)) {                  \
                    bs2 = bs1; bi2 = bi1;                                         \
                    if ((sc) > bs0 || ((sc) == bs0 && (ix) < bi0)) {              \
                        bs1 = bs0; bi1 = bi0; bs0 = (sc); bi0 = (ix);             \
                    } else { bs1 = (sc); bi1 = (ix); }                            \
                } else { bs2 = (sc); bi2 = (ix); }                                \
            } else { bs3 = (sc); bi3 = (ix); }                                    \
        }                                                                         \
    } while (0)

// ================= attn1: R11 form (4-way s-phase split, LDS.128 k reads) ========
__global__ __launch_bounds__(512) void attn1_kernel(const float* __restrict__ sink) {
    extern __shared__ float ks[];            // 8192 floats
    const int bh = blockIdx.y, h = bh % H_TOT;
    const int xt = (gridDim.x - 1) - blockIdx.x;
    const int t0 = xt * 128;
    const int tid = threadIdx.x;
    const int ph  = tid >> 7;                // 0..3
    const int tA = t0 + (tid & 127);

    u64 q2[32];
    {
        const ulonglong2* qp = (const ulonglong2*)&g_qf[((size_t)bh * T_LEN + tA) * DH];
#pragma unroll
        for (int i = 0; i < 16; i++) { ulonglong2 v = qp[i]; q2[2 * i] = v.x; q2[2 * i + 1] = v.y; }
    }

    float mrun = -CUDART_INF_F, lrun = 0.f;
    float ts0 = -CUDART_INF_F, ts1 = -CUDART_INF_F, ts2 = -CUDART_INF_F, ts3 = -CUDART_INF_F;
    int ti0 = 0, ti1 = 0, ti2 = 0, ti3 = 0;

    for (int s0 = 0; s0 <= t0; s0 += 128) {
        __syncthreads();
        {
            const float4* kg = (const float4*)&g_kf[((size_t)bh * T_LEN + s0) * DH];
            float4* d4 = (float4*)ks;
#pragma unroll
            for (int j = 0; j < 4; j++) d4[tid + j * 512] = kg[tid + j * 512];
        }
        __syncthreads();

        const int sMax = min(tA, s0 + 127);
        for (int s = s0 + ph; s <= sMax; s += 4) {
            const ulonglong2* kr = (const ulonglong2*)(ks + (s - s0) * DH);
            u64 a0 = 0ull, a1 = 0ull, a2 = 0ull, a3 = 0ull;
#pragma unroll
            for (int i = 0; i < 16; i += 4) {
                ulonglong2 k01 = kr[i];
                ulonglong2 k23 = kr[i + 1];
                ulonglong2 k45 = kr[i + 2];
                ulonglong2 k67 = kr[i + 3];
                a0 = f2fma(q2[2 * i],     k01.x, a0);
                a1 = f2fma(q2[2 * i + 1], k01.y, a1);
                a2 = f2fma(q2[2 * i + 2], k23.x, a2);
                a3 = f2fma(q2[2 * i + 3], k23.y, a3);
                a0 = f2fma(q2[2 * i + 4], k45.x, a0);
                a1 = f2fma(q2[2 * i + 5], k45.y, a1);
                a2 = f2fma(q2[2 * i + 6], k67.x, a2);
                a3 = f2fma(q2[2 * i + 7], k67.y, a3);
            }
            u64 s01 = f2add(a0, a1);
            u64 s23 = f2add(a2, a3);
            float2 sv = f2unpack(f2add(s01, s23));
            float sc = (sv.x + sv.y) * 0.125f;
            SMTK_UPDATE(sc, s, mrun, lrun, ts0, ts1, ts2, ts3, ti0, ti1, ti2, ti3);
        }
    }

    // ---- merge 4 phases per row ----
    __syncthreads();
    float* Pm = ks;
    float* Pl = ks + 512;
    float* Ps = ks + 1024;
    int*   Pi = (int*)(ks + 3072);
    Pm[tid] = mrun; Pl[tid] = lrun;
    Ps[tid * 4 + 0] = ts0; Ps[tid * 4 + 1] = ts1; Ps[tid * 4 + 2] = ts2; Ps[tid * 4 + 3] = ts3;
    Pi[tid * 4 + 0] = ti0; Pi[tid * 4 + 1] = ti1; Pi[tid * 4 + 2] = ti2; Pi[tid * 4 + 3] = ti3;
    __syncthreads();

    if (tid < 128) {
        float m0v = Pm[tid], m1v = Pm[tid + 128], m2v = Pm[tid + 256], m3v = Pm[tid + 384];
        float mm = fmaxf(fmaxf(m0v, m1v), fmaxf(m2v, m3v));
        float ll = Pl[tid]       * __expf(m0v - mm)
                 + Pl[tid + 128] * __expf(m1v - mm)
                 + Pl[tid + 256] * __expf(m2v - mm)
                 + Pl[tid + 384] * __expf(m3v - mm);

        float bs0 = -CUDART_INF_F, bs1 = -CUDART_INF_F, bs2 = -CUDART_INF_F, bs3 = -CUDART_INF_F;
        int bi0 = 0x7fffffff, bi1 = 0x7fffffff, bi2 = 0x7fffffff, bi3 = 0x7fffffff;
#pragma unroll
        for (int pp = 0; pp < 4; pp++) {
            const int pidx = pp * 128 + tid;
#pragma unroll
            for (int j = 0; j < 4; j++) {
                float sc = Ps[pidx * 4 + j];
                int   ix = Pi[pidx * 4 + j];
                MERGE_INS(sc, ix);
            }
        }
        if (bi0 == 0x7fffffff) bi0 = 0;
        if (bi1 == 0x7fffffff) bi1 = 0;
        if (bi2 == 0x7fffffff) bi2 = 0;
        if (bi3 == 0x7fffffff) bi3 = 0;

        const float skv = sink[h];
        const float mf = fmaxf(mm, skv);
        const float Z = ll * __expf(mm - mf) + __expf(skv - mf);
        const float invZ = 1.0f / Z;
        float p0 = __expf(bs0 - mf) * invZ;
        float p1 = __expf(bs1 - mf) * invZ;
        float p2 = __expf(bs2 - mf) * invZ;
        float p3 = __expf(bs3 - mf) * invZ;
        const float winv = 1.0f / (p0 + p1 + p2 + p3 + 1e-9f);
        const int o = bh * T_LEN + t0 + tid;
        g_topi[o]  = make_int4(bi0, bi1, bi2, bi3);
        g_topw[o]  = make_float4(p0 * winv, p1 * winv, p2 * winv, p3 * winv);
        g_psink[o] = __expf(skv - mf) * invZ;
    }
}

// ================= attn2: smem form, V2t stride 68 (LDS.128 outer reads) =========
__global__ __launch_bounds__(256) void attn2_kernel(const float* __restrict__ vnull,
                                                    const float* __restrict__ V1w,
                                                    const float* __restrict__ V1b,
                                                    const float* __restrict__ V2w,
                                                    const float* __restrict__ V2b) {
    extern __shared__ float sm2[];
    float* V1s = sm2;                 // 16384
    float* V2t = sm2 + 16384;         // 256*68
    __shared__ float sV1b[256];
    __shared__ float sV2b[64];

    const int bh = blockIdx.y, b = bh / H_TOT, h = bh % H_TOT;
    const int t = blockIdx.x * 256 + threadIdx.x;

    for (int i = threadIdx.x; i < 4096; i += 256) ((float4*)V1s)[i] = ((const float4*)V1w)[i];
    for (int i = threadIdx.x; i < 16384; i += 256) {
        int dd = i >> 8, j = i & 255;
        V2t[j * 68 + dd] = V2w[i];
    }
    if (threadIdx.x < 256) sV1b[threadIdx.x] = V1b[threadIdx.x];
    if (threadIdx.x < 64)  sV2b[threadIdx.x] = V2b[threadIdx.x];
    __syncthreads();

    const int o = bh * T_LEN + t;
    const int4 ti = g_topi[o];
    const float4 pw = g_topw[o];
    const float psink = g_psink[o];

    u64 mk[32];
    {
        const float4* kp0 = (const float4*)&g_kf[((size_t)bh * T_LEN + ti.x) * DH];
        const float4* kp1 = (const float4*)&g_kf[((size_t)bh * T_LEN + ti.y) * DH];
        const float4* kp2 = (const float4*)&g_kf[((size_t)bh * T_LEN + ti.z) * DH];
        const float4* kp3 = (const float4*)&g_kf[((size_t)bh * T_LEN + ti.w) * DH];
#pragma unroll
        for (int i = 0; i < 16; i++) {
            float4 a = kp0[i], c = kp1[i], e = kp2[i], f = kp3[i];
            float v0 = pw.x * a.x + pw.y * c.x + pw.z * e.x + pw.w * f.x;
            float v1 = pw.x * a.y + pw.y * c.y + pw.z * e.y + pw.w * f.y;
            float v2 = pw.x * a.z + pw.y * c.z + pw.z * e.z + pw.w * f.z;
            float v3 = pw.x * a.w + pw.y * c.w + pw.z * e.w + pw.w * f.w;
            mk[2 * i]     = f2pack(v0, v1);
            mk[2 * i + 1] = f2pack(v2, v3);
        }
    }

    u64 out2[32];
#pragma unroll
    for (int i = 0; i < 32; i++) out2[i] = *(const u64*)&sV2b[2 * i];

    for (int j = 0; j < 256; ++j) {
        const ulonglong2* v1 = (const ulonglong2*)(V1s + j * 64);
        u64 z0 = 0ull, z1 = 0ull, z2 = 0ull, z3 = 0ull;
#pragma unroll
        for (int i = 0; i < 16; i += 2) {
            ulonglong2 va = v1[i];
            ulonglong2 vb = v1[i + 1];
            z0 = f2fma(mk[2 * i],     va.x, z0);
            z1 = f2fma(mk[2 * i + 1], va.y, z1);
            z2 = f2fma(mk[2 * i + 2], vb.x, z2);
            z3 = f2fma(mk[2 * i + 3], vb.y, z3);
        }
        float z = ((f2sum(z0) + f2sum(z1)) + (f2sum(z2) + f2sum(z3))) + sV1b[j];
        float gl = 0.5f * z * (1.0f + erff(z * 0.70710678118f));
        u64 g2 = f2pack(gl, gl);
        const ulonglong2* v2 = (const ulonglong2*)(V2t + j * 68);   // 68*4=272B, 16-aligned
#pragma unroll
        for (int i = 0; i < 16; i++) {
            ulonglong2 vv = v2[i];
            out2[2 * i]     = f2fma(g2, vv.x, out2[2 * i]);
            out2[2 * i + 1] = f2fma(g2, vv.y, out2[2 * i + 1]);
        }
    }

    const int br = h / 12, hj = h % 12;
    float* outp = &g_ctx[((size_t)(b * T_LEN + t)) * NQ + br * D_MODEL + hj * 64];
    const float* vn = vnull + h * 64;
#pragma unroll
    for (int i = 0; i < 32; i++) {
        float2 v = f2unpack(out2[i]);
        v.x = fmaf(psink, vn[2 * i], v.x);
        v.y = fmaf(psink, vn[2 * i + 1], v.y);
        ((float2*)outp)[i] = v;
    }
}

// ================= launcher =================
extern "C" void kernel_launch(void* const* d_in, const int* in_sizes, int n_in,
                              void* d_out, int out_size) {
    const float* A      = (const float*)d_in[0];
    const float* X      = (const float*)d_in[1];
    const float* WKw    = (const float*)d_in[2];
    const float* WKb    = (const float*)d_in[3];
    const float* WQw    = (const float*)d_in[4];
    const float* wedgeA = (const float*)d_in[5];
    const float* wbias  = (const float*)d_in[6];
    const float* sink   = (const float*)d_in[7];
    const float* vnull  = (const float*)d_in[8];
    const float* V1w    = (const float*)d_in[9];
    const float* V1b    = (const float*)d_in[10];
    const float* V2w    = (const float*)d_in[11];
    const float* V2b    = (const float*)d_in[12];
    const float* WOw    = (const float*)d_in[13];
    const float* WOb    = (const float*)d_in[14];
    float* Y = (float*)d_out;

    const int attn2_smem = (16384 + 256 * 68) * 4;   // 135168
    cudaFuncSetAttribute(gemm_tf32_kernel<0>, cudaFuncAttributeMaxDynamicSharedMemorySize, 51200);
    cudaFuncSetAttribute(gemm_tf32_kernel<2>, cudaFuncAttributeMaxDynamicSharedMemorySize, 51200);
    cudaFuncSetAttribute(attn1_kernel, cudaFuncAttributeMaxDynamicSharedMemorySize, 32768);
    cudaFuncSetAttribute(attn2_kernel, cudaFuncAttributeMaxDynamicSharedMemorySize, attn2_smem);
    cudaFuncSetAttribute(kwr_kernel,   cudaFuncAttributeMaxDynamicSharedMemorySize, 50176);

    // 1) WQ fold + WO relayout + rope table
    prep_w<<<3008, 256>>>(WQw, wedgeA, wbias, WOw);
    // 2) fused Q projection + K base projection (one wave-balanced launch)
    gemm_tf32_kernel<0><<<dim3(60, 16), 256, 51200>>>(A, X, WKw, WKb, 768);
    // 3) K wedge + rope (48 head variants)
    kwr_kernel<<<dim3(16, 48), 128, 50176>>>(wedgeA, wbias);
    // 4) attention scores / softmax / top-4   (<- ncu capture slot)
    attn1_kernel<<<dim3(8, 96), 512, 32768>>>(sink);
    // 5) marker + MLP + sink
    attn2_kernel<<<dim3(4, 96), 256, attn2_smem>>>(vnull, V1w, V1b, V2w, V2b);
    // 6) output projection, split-K over branches
    gemm_tf32_kernel<2><<<dim3(12, 16, 4), 256, 51200>>>(nullptr, nullptr, nullptr, nullptr, 768);
    // 7) combine partials + bias
    reduce_kernel<<<1536, 256>>>(WOb, Y);
}

// round 17
// speedup vs baseline: 1.4551x; 1.0106x over previous
#include <cuda_runtime.h>
#include <math.h>
#include <math_constants.h>

#define D_MODEL 768
#define N_BR    4
#define DH      64
#define H_TOT   48
#define BATCH   2
#define T_LEN   1024
#define M_ROWS  2048
#define NQ      3072

typedef unsigned long long u64;
typedef unsigned int u32;

// ---- packed fp32x2 helpers ----
__device__ __forceinline__ u64 f2fma(u64 a, u64 b, u64 c) {
    u64 d; asm("fma.rn.f32x2 %0, %1, %2, %3;" : "=l"(d) : "l"(a), "l"(b), "l"(c)); return d;
}
__device__ __forceinline__ u64 f2add(u64 a, u64 b) {
    u64 d; asm("add.rn.f32x2 %0, %1, %2;" : "=l"(d) : "l"(a), "l"(b)); return d;
}
__device__ __forceinline__ u64 f2pack(float lo, float hi) {
    u64 d; asm("mov.b64 %0, {%1, %2};" : "=l"(d) : "f"(lo), "f"(hi)); return d;
}
__device__ __forceinline__ float2 f2unpack(u64 a) {
    float lo, hi; asm("mov.b64 {%0, %1}, %2;" : "=f"(lo), "=f"(hi) : "l"(a)); return make_float2(lo, hi);
}
__device__ __forceinline__ float f2sum(u64 a) { float2 v = f2unpack(a); return v.x + v.y; }

// ---- tf32 split ----
__device__ __forceinline__ float2 tf32split(float x) {
    u32 hb; asm("cvt.rna.tf32.f32 %0, %1;" : "=r"(hb) : "f"(x));
    float hf = __uint_as_float(hb);
    float lo = x - hf;
    u32 lb; asm("cvt.rna.tf32.f32 %0, %1;" : "=r"(lb) : "f"(lo));
    return make_float2(hf, __uint_as_float(lb));
}

#define MMA_TF32(ACC, A0, A1, A2, A3, B0, B1)                                        \
    asm volatile("mma.sync.aligned.m16n8k8.row.col.f32.tf32.tf32.f32 "               \
                 "{%0,%1,%2,%3}, {%4,%5,%6,%7}, {%8,%9}, {%0,%1,%2,%3};"             \
                 : "+f"(ACC[0]), "+f"(ACC[1]), "+f"(ACC[2]), "+f"(ACC[3])            \
                 : "r"(A0), "r"(A1), "r"(A2), "r"(A3), "r"(B0), "r"(B1))

// ---- scratch ----
__device__ float  g_wq2f [NQ * D_MODEL];           // folded WQ
__device__ float  g_wotf [D_MODEL * NQ];           // WO as [n][br*768+c]
__device__ float  g_kbase[(size_t)M_ROWS * D_MODEL];
__device__ float  g_qf   [(size_t)M_ROWS * NQ];
__device__ float  g_kf   [(size_t)M_ROWS * NQ];
__device__ float  g_ctx  [(size_t)M_ROWS * NQ];
__device__ float  g_part [(size_t)N_BR * M_ROWS * D_MODEL];
__device__ float2 g_ropetab[T_LEN * 32];
__device__ int4   g_topi [BATCH * H_TOT * T_LEN];
__device__ float4 g_topw [BATCH * H_TOT * T_LEN];
__device__ float  g_psink[BATCH * H_TOT * T_LEN];

// ================= prep_w: WQ wedge fold + WO relayout + rope table ==============
__global__ __launch_bounds__(256) void prep_w(const float* __restrict__ WQw,
                                              const float* __restrict__ wedgeA,
                                              const float* __restrict__ wbias,
                                              const float* __restrict__ WOw) {
    __shared__ float sk[4096];
    __shared__ float Ws[64 * 68];
    __shared__ float tile[32][33];
    const int blk = blockIdx.x, tid = threadIdx.x;

    if (blk < 576) {
        const int h = blk / 12, c0 = (blk % 12) * 64;
        for (int i = tid; i < 4096; i += 256) {
            int e = i >> 6, d = i & 63;
            sk[i] = wedgeA[e * 64 + d] - wedgeA[d * 64 + e];
        }
        for (int i = tid; i < 4096; i += 256) {
            int e = i >> 6, c = i & 63;
            Ws[e * 68 + c] = WQw[(size_t)(h * 64 + e) * D_MODEL + c0 + c];
        }
        __syncthreads();
        const int d = tid >> 2, cg = (tid & 3) * 16;
        float outv[16];
        const float bd = 1.0f + wbias[h * 64 + d];
#pragma unroll
        for (int u = 0; u < 16; u++) outv[u] = bd * Ws[d * 68 + cg + u];
        for (int e = 0; e < 64; ++e) {
            float s = sk[e * 64 + d];
            const float* wr = &Ws[e * 68 + cg];
#pragma unroll
            for (int u = 0; u < 16; u++) outv[u] = fmaf(s, wr[u], outv[u]);
        }
        float* dst = g_wq2f + (size_t)(h * 64 + d) * D_MODEL + c0 + cg;
#pragma unroll
        for (int u = 0; u < 16; u++) dst[u] = outv[u];
    } else if (blk < 2880) {
        const int b3 = blk - 576;
        const int br = b3 / 576, rem = b3 % 576;
        const int cb = (rem / 24) * 32, nb = (rem % 24) * 32;
        const int tx = tid & 31, ty = tid >> 5;
        for (int r = ty; r < 32; r += 8)
            tile[r][tx] = WOw[((size_t)br * D_MODEL + cb + r) * D_MODEL + nb + tx];
        __syncthreads();
        for (int r = ty; r < 32; r += 8)
            g_wotf[(size_t)(nb + r) * NQ + br * D_MODEL + cb + tx] = tile[tx][r];
    } else {
        int idx = (blk - 2880) * 256 + tid;
        int t = idx >> 5, i = idx & 31;
        float inv = exp2f(-(float)i * 0.41524101186092034f);
        float fr = (float)t * inv;
        g_ropetab[idx] = make_float2(cosf(fr), sinf(fr));
    }
}

// ================= tf32-3x NT GEMM, double-buffered, paired-k smem layout ========
// smem layout (float2 units):
//   A: 8 groups (G*4+P), row = 260 float2; element (k,m): G=k>>3,P=k&3,H=(k&7)>>2
//      addr = (G*4+P)*260 + m*2 + H.   buffer stride 2080 float2.
//   B: 8 groups, row = 132 float2; element (k,c): addr = (G*4+P)*132 + c*2 + H.
//      buffer stride 1056 float2.
// Fragment loads are LDS.128 (pairs k,k+4 adjacent); verified conflict-free.
// MODE 0 (fused QK): bx<48: Q proj head bx -> rope -> g_qf
//                    bx>=48: K base n-tile (bx-48) -> +bias -> g_kbase
// MODE 2: out proj split-K: z=br slice -> g_part
template <int MODE>
__global__ __launch_bounds__(256) void gemm_tf32_kernel(const float* __restrict__ A0,
                                                        const float* __restrict__ A1,
                                                        const float* __restrict__ B1,
                                                        const float* __restrict__ aux,
                                                        int K) {
    extern __shared__ float2 smg[];
    float2* Abuf = smg;            // 2 x 2080
    float2* Bbuf = smg + 4160;     // 2 x 1056

    const int tid = threadIdx.x;
    const int m0 = blockIdx.y * 128;
    const int warpId = tid >> 5, lane = tid & 31;
    const int warpM = warpId & 3, warpN = warpId >> 2;
    const int g = lane >> 2, tg = lane & 3;
    const int sa_m = tid >> 1, sa_g = tid & 1;           // A: row, k-group
    const int sb_n = tid & 63, sb_k = (tid >> 6) * 4;    // B: col, k-base
    const int sb_G = sb_k >> 3, sb_H = (sb_k >> 2) & 1;

    const float* Aop;
    const float* Bop;
    int ldA, ldB, n0;
    bool isQ = true;
    if (MODE == 0) {
        isQ = blockIdx.x < 48;
        n0 = (isQ ? blockIdx.x : (blockIdx.x - 48)) * 64;
        Aop = isQ ? A0 : A1;
        Bop = isQ ? g_wq2f : B1;
        ldA = 768; ldB = 768;
    } else {
        n0 = blockIdx.x * 64;
        Aop = g_ctx  + blockIdx.z * 768;
        Bop = g_wotf + blockIdx.z * 768;
        ldA = 3072; ldB = 3072;
    }

    float acc[2][4][4];
#pragma unroll
    for (int mf = 0; mf < 2; mf++)
#pragma unroll
        for (int nf = 0; nf < 4; nf++)
#pragma unroll
            for (int r = 0; r < 4; r++) acc[mf][nf][r] = 0.f;

    const float* Arow = Aop + (size_t)(m0 + sa_m) * ldA + sa_g * 8;
    const float* Brow = Bop + (size_t)(n0 + sb_n) * ldB + sb_k;

    float4 pa0 = *(const float4*)(Arow);
    float4 pa1 = *(const float4*)(Arow + 4);
    float4 pb  = *(const float4*)(Brow);

    // stage buffer 0
    {
        float av[8] = {pa0.x, pa0.y, pa0.z, pa0.w, pa1.x, pa1.y, pa1.z, pa1.w};
        float4* A4 = (float4*)Abuf;
#pragma unroll
        for (int jj = 0; jj < 4; jj++) {
            float2 s0 = tf32split(av[jj]);
            float2 s1 = tf32split(av[jj + 4]);
            A4[(sa_g * 4 + jj) * 130 + sa_m] = make_float4(s0.x, s0.y, s1.x, s1.y);
        }
        float bv[4] = {pb.x, pb.y, pb.z, pb.w};
#pragma unroll
        for (int j = 0; j < 4; j++)
            Bbuf[(sb_G * 4 + j) * 132 + sb_n * 2 + sb_H] = tf32split(bv[j]);
    }
    __syncthreads();

    int p = 0;
    for (int k0 = 0; k0 < K; k0 += 16) {
        const bool more = (k0 + 16) < K;
        if (more) {
            pa0 = *(const float4*)(Arow + k0 + 16);
            pa1 = *(const float4*)(Arow + k0 + 20);
            pb  = *(const float4*)(Brow + k0 + 16);
        }
        const float4* A4r = (const float4*)(Abuf + p * 2080);
        const float4* B4r = (const float4*)(Bbuf + p * 1056);
#pragma unroll
        for (int ks = 0; ks < 16; ks += 8) {
            const int Gg = ks >> 3;
            const float4* Ag = A4r + (size_t)(Gg * 4 + tg) * 130;
            const float4* Bg = B4r + (size_t)(Gg * 4 + tg) * 66;
            float4 fa4[2][2];
#pragma unroll
            for (int mf = 0; mf < 2; mf++) {
                const int rI = warpM * 32 + mf * 16 + g;
                fa4[mf][0] = Ag[rI];
                fa4[mf][1] = Ag[rI + 8];
            }
            float4 fb4[4];
#pragma unroll
            for (int nf = 0; nf < 4; nf++) {
                const int cI = warpN * 32 + nf * 8 + g;
                fb4[nf] = Bg[cI];
            }
#pragma unroll
            for (int mf = 0; mf < 2; mf++) {
                const u32 ah0 = __float_as_uint(fa4[mf][0].x), al0 = __float_as_uint(fa4[mf][0].y);
                const u32 ah1 = __float_as_uint(fa4[mf][1].x), al1 = __float_as_uint(fa4[mf][1].y);
                const u32 ah2 = __float_as_uint(fa4[mf][0].z), al2 = __float_as_uint(fa4[mf][0].w);
                const u32 ah3 = __float_as_uint(fa4[mf][1].z), al3 = __float_as_uint(fa4[mf][1].w);
#pragma unroll
                for (int nf = 0; nf < 4; nf++) {
                    const u32 bh0 = __float_as_uint(fb4[nf].x), bl0 = __float_as_uint(fb4[nf].y);
                    const u32 bh1 = __float_as_uint(fb4[nf].z), bl1 = __float_as_uint(fb4[nf].w);
                    MMA_TF32(acc[mf][nf], al0, al1, al2, al3, bh0, bh1);
                    MMA_TF32(acc[mf][nf], ah0, ah1, ah2, ah3, bl0, bl1);
                    MMA_TF32(acc[mf][nf], ah0, ah1, ah2, ah3, bh0, bh1);
                }
            }
        }
        if (more) {
            float2* Bn = Bbuf + (p ^ 1) * 1056;
            float4* An4 = (float4*)(Abuf + (p ^ 1) * 2080);
            float av[8] = {pa0.x, pa0.y, pa0.z, pa0.w, pa1.x, pa1.y, pa1.z, pa1.w};
#pragma unroll
            for (int jj = 0; jj < 4; jj++) {
                float2 s0 = tf32split(av[jj]);
                float2 s1 = tf32split(av[jj + 4]);
                An4[(sa_g * 4 + jj) * 130 + sa_m] = make_float4(s0.x, s0.y, s1.x, s1.y);
            }
            float bv[4] = {pb.x, pb.y, pb.z, pb.w};
#pragma unroll
            for (int j = 0; j < 4; j++)
                Bn[(sb_G * 4 + j) * 132 + sb_n * 2 + sb_H] = tf32split(bv[j]);
            __syncthreads();
        }
        p ^= 1;
    }

    // ---- epilogue ----
#pragma unroll
    for (int mf = 0; mf < 2; mf++) {
#pragma unroll
        for (int nf = 0; nf < 4; nf++) {
            const int r0 = m0 + warpM * 32 + mf * 16 + g;
            const int r1 = r0 + 8;
            float c0 = acc[mf][nf][0], c1 = acc[mf][nf][1];
            float c2 = acc[mf][nf][2], c3 = acc[mf][nf][3];
            if (MODE == 0) {
                if (isQ) {
                    const int h = blockIdx.x;
                    const int i = warpN * 16 + nf * 4 + tg;
                    {
                        const int t = r0 & 1023, bb = r0 >> 10;
                        float2 rc = g_ropetab[t * 32 + i];
                        float* qp = &g_qf[(((size_t)(bb * H_TOT + h)) * T_LEN + t) * DH];
                        qp[i]      = c0 * rc.x - c1 * rc.y;
                        qp[i + 32] = c0 * rc.y + c1 * rc.x;
                    }
                    {
                        const int t = r1 & 1023, bb = r1 >> 10;
                        float2 rc = g_ropetab[t * 32 + i];
                        float* qp = &g_qf[(((size_t)(bb * H_TOT + h)) * T_LEN + t) * DH];
                        qp[i]      = c2 * rc.x - c3 * rc.y;
                        qp[i + 32] = c2 * rc.y + c3 * rc.x;
                    }
                } else {
                    const int nc = n0 + warpN * 32 + nf * 8 + 2 * tg;
                    const float b0 = aux[nc], b1 = aux[nc + 1];
                    *(float2*)&g_kbase[(size_t)r0 * 768 + nc] = make_float2(c0 + b0, c1 + b1);
                    *(float2*)&g_kbase[(size_t)r1 * 768 + nc] = make_float2(c2 + b0, c3 + b1);
                }
            } else {
                const int nc = n0 + warpN * 32 + nf * 8 + 2 * tg;
                float* base = g_part + (size_t)blockIdx.z * M_ROWS * D_MODEL;
                *(float2*)&base[(size_t)r0 * 768 + nc] = make_float2(c0, c1);
                *(float2*)&base[(size_t)r1 * 768 + nc] = make_float2(c2, c3);
            }
        }
    }
}

// ================= kwr: per-head K wedge + rope (kbase -> g_kf) ==================
__global__ __launch_bounds__(128) void kwr_kernel(const float* __restrict__ wedgeA,
                                                  const float* __restrict__ wbias) {
    extern __shared__ float kwr_sm[];
    float* Ms  = kwr_sm;            // 4096
    float* kbs = kwr_sm + 4096;     // 128*65
    const int h = blockIdx.y, hj = h % 12;
    const int m0 = blockIdx.x * 128;
    const int tid = threadIdx.x;

    for (int i = tid; i < 4096; i += 128) {
        int e = i >> 6, d = i & 63;
        float v = wedgeA[e * 64 + d] - wedgeA[d * 64 + e];
        if (e == d) v += 1.0f + wbias[h * 64 + d];
        Ms[i] = v;
    }
    for (int i = tid; i < 2048; i += 128) {
        int r = i >> 4, c4 = (i & 15) * 4;
        float4 v = *(const float4*)&g_kbase[(size_t)(m0 + r) * 768 + hj * 64 + c4];
        float* dst = &kbs[r * 65 + c4];
        dst[0] = v.x; dst[1] = v.y; dst[2] = v.z; dst[3] = v.w;
    }
    __syncthreads();

    const int m = m0 + tid, b = m >> 10, t = m & 1023;
    u64 acc2[32];
#pragma unroll
    for (int i = 0; i < 32; i++) acc2[i] = 0ull;
    const float* kr = &kbs[tid * 65];
    for (int e = 0; e < 64; ++e) {
        float kv = kr[e];
        u64 kv2 = f2pack(kv, kv);
        const u64* ms = (const u64*)&Ms[e * 64];
#pragma unroll
        for (int i = 0; i < 32; i++) acc2[i] = f2fma(kv2, ms[i], acc2[i]);
    }
    float* kp = &g_kf[(((size_t)(b * H_TOT + h)) * T_LEN + t) * DH];
    const float2* rt = &g_ropetab[t * 32];
#pragma unroll
    for (int i = 0; i < 32; i++) {
        float2 w = f2unpack(acc2[i]);
        float2 rc = rt[i];
        kp[i]      = w.x * rc.x - w.y * rc.y;
        kp[i + 32] = w.x * rc.y + w.y * rc.x;
    }
}

// ================= reduce =================
__global__ __launch_bounds__(256) void reduce_kernel(const float* __restrict__ WOb,
                                                     float* __restrict__ Y) {
    const size_t i4 = (size_t)blockIdx.x * 256 + threadIdx.x;
    const size_t base = i4 * 4;
    const int nc = (int)(base % 768);
    float4 p0 = *(const float4*)&g_part[base];
    float4 p1 = *(const float4*)&g_part[base + (size_t)M_ROWS * D_MODEL];
    float4 p2 = *(const float4*)&g_part[base + (size_t)2 * M_ROWS * D_MODEL];
    float4 p3 = *(const float4*)&g_part[base + (size_t)3 * M_ROWS * D_MODEL];
    float4 o;
    o.x = 0.25f * (p0.x + p1.x + p2.x + p3.x) + 0.25f * (WOb[nc]     + WOb[768 + nc]     + WOb[1536 + nc]     + WOb[2304 + nc]);
    o.y = 0.25f * (p0.y + p1.y + p2.y + p3.y) + 0.25f * (WOb[nc + 1] + WOb[768 + nc + 1] + WOb[1536 + nc + 1] + WOb[2304 + nc + 1]);
    o.z = 0.25f * (p0.z + p1.z + p2.z + p3.z) + 0.25f * (WOb[nc + 2] + WOb[768 + nc + 2] + WOb[1536 + nc + 2] + WOb[2304 + nc + 2]);
    o.w = 0.25f * (p0.w + p1.w + p2.w + p3.w) + 0.25f * (WOb[nc + 3] + WOb[768 + nc + 3] + WOb[1536 + nc + 3] + WOb[2304 + nc + 3]);
    *(float4*)&Y[base] = o;
}

// ---- online softmax + top-4 update ----
#define SMTK_UPDATE(sc, sidx, mrun, lrun, s0v, s1v, s2v, s3v, i0v, i1v, i2v, i3v) \
    do {                                                                          \
        if ((sc) <= (mrun)) { (lrun) += __expf((sc) - (mrun)); }                  \
        else { (lrun) = fmaf((lrun), __expf((mrun) - (sc)), 1.0f); (mrun) = (sc); } \
        if ((sc) > (s3v)) {                                                       \
            if ((sc) > (s2v)) {                                                   \
                (s3v) = (s2v); (i3v) = (i2v);                                     \
                if ((sc) > (s1v)) {                                               \
                    (s2v) = (s1v); (i2v) = (i1v);                                 \
                    if ((sc) > (s0v)) {                                           \
                        (s1v) = (s0v); (i1v) = (i0v);                             \
                        (s0v) = (sc); (i0v) = (sidx);                             \
                    } else { (s1v) = (sc); (i1v) = (sidx); }                      \
                } else { (s2v) = (sc); (i2v) = (sidx); }                          \
            } else { (s3v) = (sc); (i3v) = (sidx); }                              \
        }                                                                         \
    } while (0)

#define MERGE_INS(sc, ix)                                                         \
    do {                                                                          \
        if ((sc) > bs3 || ((sc) == bs3 && (ix) < bi3)) {                          \
            if ((sc) > bs2 || ((sc) == bs2 && (ix) < bi2)) {                      \
                bs3 = bs2; bi3 = bi2;                                             \
                if ((sc) > bs1 || ((sc) == bs1 && (ix) < bi1)) {                  \
                    bs2 = bs1; bi2 = bi1;                                         \
                    if ((sc) > bs0 || ((sc) == bs0 && (ix) < bi0)) {              \
                        bs1 = bs0; bi1 = bi0; bs0 = (sc); bi0 = (ix);             \
                    } else { bs1 = (sc); bi1 = (ix); }                            \
                } else { bs2 = (sc); bi2 = (ix); }                                \
            } else { bs3 = (sc); bi3 = (ix); }                                    \
        }                                                                         \
    } while (0)

// ================= attn1: R11 form (4-way s-phase split, LDS.128 k reads) ========
__global__ __launch_bounds__(512) void attn1_kernel(const float* __restrict__ sink) {
    extern __shared__ float ks[];            // 8192 floats
    const int bh = blockIdx.y, h = bh % H_TOT;
    const int xt = (gridDim.x - 1) - blockIdx.x;
    const int t0 = xt * 128;
    const int tid = threadIdx.x;
    const int ph  = tid >> 7;                // 0..3
    const int tA = t0 + (tid & 127);

    u64 q2[32];
    {
        const ulonglong2* qp = (const ulonglong2*)&g_qf[((size_t)bh * T_LEN + tA) * DH];
#pragma unroll
        for (int i = 0; i < 16; i++) { ulonglong2 v = qp[i]; q2[2 * i] = v.x; q2[2 * i + 1] = v.y; }
    }

    float mrun = -CUDART_INF_F, lrun = 0.f;
    float ts0 = -CUDART_INF_F, ts1 = -CUDART_INF_F, ts2 = -CUDART_INF_F, ts3 = -CUDART_INF_F;
    int ti0 = 0, ti1 = 0, ti2 = 0, ti3 = 0;

    for (int s0 = 0; s0 <= t0; s0 += 128) {
        __syncthreads();
        {
            const float4* kg = (const float4*)&g_kf[((size_t)bh * T_LEN + s0) * DH];
            float4* d4 = (float4*)ks;
#pragma unroll
            for (int j = 0; j < 4; j++) d4[tid + j * 512] = kg[tid + j * 512];
        }
        __syncthreads();

        const int sMax = min(tA, s0 + 127);
        for (int s = s0 + ph; s <= sMax; s += 4) {
            const ulonglong2* kr = (const ulonglong2*)(ks + (s - s0) * DH);
            u64 a0 = 0ull, a1 = 0ull, a2 = 0ull, a3 = 0ull;
#pragma unroll
            for (int i = 0; i < 16; i += 4) {
                ulonglong2 k01 = kr[i];
                ulonglong2 k23 = kr[i + 1];
                ulonglong2 k45 = kr[i + 2];
                ulonglong2 k67 = kr[i + 3];
                a0 = f2fma(q2[2 * i],     k01.x, a0);
                a1 = f2fma(q2[2 * i + 1], k01.y, a1);
                a2 = f2fma(q2[2 * i + 2], k23.x, a2);
                a3 = f2fma(q2[2 * i + 3], k23.y, a3);
                a0 = f2fma(q2[2 * i + 4], k45.x, a0);
                a1 = f2fma(q2[2 * i + 5], k45.y, a1);
                a2 = f2fma(q2[2 * i + 6], k67.x, a2);
                a3 = f2fma(q2[2 * i + 7], k67.y, a3);
            }
            u64 s01 = f2add(a0, a1);
            u64 s23 = f2add(a2, a3);
            float2 sv = f2unpack(f2add(s01, s23));
            float sc = (sv.x + sv.y) * 0.125f;
            SMTK_UPDATE(sc, s, mrun, lrun, ts0, ts1, ts2, ts3, ti0, ti1, ti2, ti3);
        }
    }

    // ---- merge 4 phases per row ----
    __syncthreads();
    float* Pm = ks;
    float* Pl = ks + 512;
    float* Ps = ks + 1024;
    int*   Pi = (int*)(ks + 3072);
    Pm[tid] = mrun; Pl[tid] = lrun;
    Ps[tid * 4 + 0] = ts0; Ps[tid * 4 + 1] = ts1; Ps[tid * 4 + 2] = ts2; Ps[tid * 4 + 3] = ts3;
    Pi[tid * 4 + 0] = ti0; Pi[tid * 4 + 1] = ti1; Pi[tid * 4 + 2] = ti2; Pi[tid * 4 + 3] = ti3;
    __syncthreads();

    if (tid < 128) {
        float m0v = Pm[tid], m1v = Pm[tid + 128], m2v = Pm[tid + 256], m3v = Pm[tid + 384];
        float mm = fmaxf(fmaxf(m0v, m1v), fmaxf(m2v, m3v));
        float ll = Pl[tid]       * __expf(m0v - mm)
                 + Pl[tid + 128] * __expf(m1v - mm)
                 + Pl[tid + 256] * __expf(m2v - mm)
                 + Pl[tid + 384] * __expf(m3v - mm);

        float bs0 = -CUDART_INF_F, bs1 = -CUDART_INF_F, bs2 = -CUDART_INF_F, bs3 = -CUDART_INF_F;
        int bi0 = 0x7fffffff, bi1 = 0x7fffffff, bi2 = 0x7fffffff, bi3 = 0x7fffffff;
#pragma unroll
        for (int pp = 0; pp < 4; pp++) {
            const int pidx = pp * 128 + tid;
#pragma unroll
            for (int j = 0; j < 4; j++) {
                float sc = Ps[pidx * 4 + j];
                int   ix = Pi[pidx * 4 + j];
                MERGE_INS(sc, ix);
            }
        }
        if (bi0 == 0x7fffffff) bi0 = 0;
        if (bi1 == 0x7fffffff) bi1 = 0;
        if (bi2 == 0x7fffffff) bi2 = 0;
        if (bi3 == 0x7fffffff) bi3 = 0;

        const float skv = sink[h];
        const float mf = fmaxf(mm, skv);
        const float Z = ll * __expf(mm - mf) + __expf(skv - mf);
        const float invZ = 1.0f / Z;
        float p0 = __expf(bs0 - mf) * invZ;
        float p1 = __expf(bs1 - mf) * invZ;
        float p2 = __expf(bs2 - mf) * invZ;
        float p3 = __expf(bs3 - mf) * invZ;
        const float winv = 1.0f / (p0 + p1 + p2 + p3 + 1e-9f);
        const int o = bh * T_LEN + t0 + tid;
        g_topi[o]  = make_int4(bi0, bi1, bi2, bi3);
        g_topw[o]  = make_float4(p0 * winv, p1 * winv, p2 * winv, p3 * winv);
        g_psink[o] = __expf(skv - mf) * invZ;
    }
}

// ================= attn2: smem form, V2t stride 68 (LDS.128 outer reads) =========
__global__ __launch_bounds__(256) void attn2_kernel(const float* __restrict__ vnull,
                                                    const float* __restrict__ V1w,
                                                    const float* __restrict__ V1b,
                                                    const float* __restrict__ V2w,
                                                    const float* __restrict__ V2b) {
    extern __shared__ float sm2[];
    float* V1s = sm2;                 // 16384
    float* V2t = sm2 + 16384;         // 256*68
    __shared__ float sV1b[256];
    __shared__ float sV2b[64];

    const int bh = blockIdx.y, b = bh / H_TOT, h = bh % H_TOT;
    const int t = blockIdx.x * 256 + threadIdx.x;

    for (int i = threadIdx.x; i < 4096; i += 256) ((float4*)V1s)[i] = ((const float4*)V1w)[i];
    for (int i = threadIdx.x; i < 16384; i += 256) {
        int dd = i >> 8, j = i & 255;
        V2t[j * 68 + dd] = V2w[i];
    }
    if (threadIdx.x < 256) sV1b[threadIdx.x] = V1b[threadIdx.x];
    if (threadIdx.x < 64)  sV2b[threadIdx.x] = V2b[threadIdx.x];
    __syncthreads();

    const int o = bh * T_LEN + t;
    const int4 ti = g_topi[o];
    const float4 pw = g_topw[o];
    const float psink = g_psink[o];

    u64 mk[32];
    {
        const float4* kp0 = (const float4*)&g_kf[((size_t)bh * T_LEN + ti.x) * DH];
        const float4* kp1 = (const float4*)&g_kf[((size_t)bh * T_LEN + ti.y) * DH];
        const float4* kp2 = (const float4*)&g_kf[((size_t)bh * T_LEN + ti.z) * DH];
        const float4* kp3 = (const float4*)&g_kf[((size_t)bh * T_LEN + ti.w) * DH];
#pragma unroll
        for (int i = 0; i < 16; i++) {
            float4 a = kp0[i], c = kp1[i], e = kp2[i], f = kp3[i];
            float v0 = pw.x * a.x + pw.y * c.x + pw.z * e.x + pw.w * f.x;
            float v1 = pw.x * a.y + pw.y * c.y + pw.z * e.y + pw.w * f.y;
            float v2 = pw.x * a.z + pw.y * c.z + pw.z * e.z + pw.w * f.z;
            float v3 = pw.x * a.w + pw.y * c.w + pw.z * e.w + pw.w * f.w;
            mk[2 * i]     = f2pack(v0, v1);
            mk[2 * i + 1] = f2pack(v2, v3);
        }
    }

    u64 out2[32];
#pragma unroll
    for (int i = 0; i < 32; i++) out2[i] = *(const u64*)&sV2b[2 * i];

    for (int j = 0; j < 256; ++j) {
        const ulonglong2* v1 = (const ulonglong2*)(V1s + j * 64);
        u64 z0 = 0ull, z1 = 0ull, z2 = 0ull, z3 = 0ull;
#pragma unroll
        for (int i = 0; i < 16; i += 2) {
            ulonglong2 va = v1[i];
            ulonglong2 vb = v1[i + 1];
            z0 = f2fma(mk[2 * i],     va.x, z0);
            z1 = f2fma(mk[2 * i + 1], va.y, z1);
            z2 = f2fma(mk[2 * i + 2], vb.x, z2);
            z3 = f2fma(mk[2 * i + 3], vb.y, z3);
        }
        float z = ((f2sum(z0) + f2sum(z1)) + (f2sum(z2) + f2sum(z3))) + sV1b[j];
        float gl = 0.5f * z * (1.0f + erff(z * 0.70710678118f));
        u64 g2 = f2pack(gl, gl);
        const ulonglong2* v2 = (const ulonglong2*)(V2t + j * 68);
#pragma unroll
        for (int i = 0; i < 16; i++) {
            ulonglong2 vv = v2[i];
            out2[2 * i]     = f2fma(g2, vv.x, out2[2 * i]);
            out2[2 * i + 1] = f2fma(g2, vv.y, out2[2 * i + 1]);
        }
    }

    const int br = h / 12, hj = h % 12;
    float* outp = &g_ctx[((size_t)(b * T_LEN + t)) * NQ + br * D_MODEL + hj * 64];
    const float* vn = vnull + h * 64;
#pragma unroll
    for (int i = 0; i < 32; i++) {
        float2 v = f2unpack(out2[i]);
        v.x = fmaf(psink, vn[2 * i], v.x);
        v.y = fmaf(psink, vn[2 * i + 1], v.y);
        ((float2*)outp)[i] = v;
    }
}

// ================= launcher =================
extern "C" void kernel_launch(void* const* d_in, const int* in_sizes, int n_in,
                              void* d_out, int out_size) {
    const float* A      = (const float*)d_in[0];
    const float* X      = (const float*)d_in[1];
    const float* WKw    = (const float*)d_in[2];
    const float* WKb    = (const float*)d_in[3];
    const float* WQw    = (const float*)d_in[4];
    const float* wedgeA = (const float*)d_in[5];
    const float* wbias  = (const float*)d_in[6];
    const float* sink   = (const float*)d_in[7];
    const float* vnull  = (const float*)d_in[8];
    const float* V1w    = (const float*)d_in[9];
    const float* V1b    = (const float*)d_in[10];
    const float* V2w    = (const float*)d_in[11];
    const float* V2b    = (const float*)d_in[12];
    const float* WOw    = (const float*)d_in[13];
    const float* WOb    = (const float*)d_in[14];
    float* Y = (float*)d_out;

    const int gemm_smem  = (2 * 2080 + 2 * 1056) * 8;    // 50176 B
    const int attn2_smem = (16384 + 256 * 68) * 4;       // 135168 B
    cudaFuncSetAttribute(gemm_tf32_kernel<0>, cudaFuncAttributeMaxDynamicSharedMemorySize, gemm_smem);
    cudaFuncSetAttribute(gemm_tf32_kernel<2>, cudaFuncAttributeMaxDynamicSharedMemorySize, gemm_smem);
    cudaFuncSetAttribute(attn1_kernel, cudaFuncAttributeMaxDynamicSharedMemorySize, 32768);
    cudaFuncSetAttribute(attn2_kernel, cudaFuncAttributeMaxDynamicSharedMemorySize, attn2_smem);
    cudaFuncSetAttribute(kwr_kernel,   cudaFuncAttributeMaxDynamicSharedMemorySize, 50176);

    // 1) WQ fold + WO relayout + rope table
    prep_w<<<3008, 256>>>(WQw, wedgeA, wbias, WOw);
    // 2) fused Q projection + K base projection
    gemm_tf32_kernel<0><<<dim3(60, 16), 256, gemm_smem>>>(A, X, WKw, WKb, 768);
    // 3) K wedge + rope (48 head variants)
    kwr_kernel<<<dim3(16, 48), 128, 50176>>>(wedgeA, wbias);
    // 4) attention scores / softmax / top-4   (<- ncu capture slot, canary)
    attn1_kernel<<<dim3(8, 96), 512, 32768>>>(sink);
    // 5) marker + MLP + sink
    attn2_kernel<<<dim3(4, 96), 256, attn2_smem>>>(vnull, V1w, V1b, V2w, V2b);
    // 6) output projection, split-K over branches
    gemm_tf32_kernel<2><<<dim3(12, 16, 4), 256, gemm_smem>>>(nullptr, nullptr, nullptr, nullptr, 768);
    // 7) combine partials + bias
    reduce_kernel<<<1536, 256>>>(WOb, Y);
}